// round 1
// baseline (speedup 1.0000x reference)
#include <cuda_runtime.h>
#include <cuda_bf16.h>
#include <cstdint>

// Problem constants
constexpr int NP = 4096;   // data_length
constexpr int KD = 8192;   // T_IN * D_IN
constexpr int FD = 2048;   // F
constexpr float GAMMA = 1.0f / 2048.0f;

// GEMM tiling
constexpr int BM = 128, BN = 128, BK = 32;
constexpr int SST = 40;            // smem row stride (bf16 elems), padded
constexpr int SBUF = 128 * SST;    // elems per smem buffer

// Scratch (device globals; no runtime allocation)
__device__ __nv_bfloat16 g_xsb[(size_t)NP * KD];  // xs in bf16        (64 MB)
__device__ __nv_bfloat16 g_Wt[(size_t)FD * KD];   // W^T in bf16       (32 MB)
__device__ __nv_bfloat16 g_Xb[(size_t)NP * FD];   // X = xs@W in bf16  (16 MB)
__device__ float g_sq[NP];
__device__ float g_bv[NP];
__device__ float g_part[32 * 32];

// ---------------------------------------------------------------------------
__device__ __forceinline__ uint32_t smem_u32(const void* p) {
    return (uint32_t)__cvta_generic_to_shared(p);
}
__device__ __forceinline__ void ldmx4(uint32_t& r0, uint32_t& r1, uint32_t& r2,
                                      uint32_t& r3, uint32_t a) {
    asm volatile("ldmatrix.sync.aligned.m8n8.x4.shared.b16 {%0,%1,%2,%3}, [%4];\n"
                 : "=r"(r0), "=r"(r1), "=r"(r2), "=r"(r3) : "r"(a));
}
__device__ __forceinline__ void mma_bf16(float c[4], const uint32_t a[4],
                                         const uint32_t b[2]) {
    asm volatile(
        "mma.sync.aligned.m16n8k16.row.col.f32.bf16.bf16.f32 "
        "{%0,%1,%2,%3}, {%4,%5,%6,%7}, {%8,%9}, {%0,%1,%2,%3};\n"
        : "+f"(c[0]), "+f"(c[1]), "+f"(c[2]), "+f"(c[3])
        : "r"(a[0]), "r"(a[1]), "r"(a[2]), "r"(a[3]), "r"(b[0]), "r"(b[1]));
}

// NT GEMM mainloop: A row-major [m][k], B row-major [n][k]; 128x128 block,
// 256 threads, 8 warps in 2(m) x 4(n), warp tile 64x32, double-buffered smem.
__device__ __forceinline__ void gemm_mainloop(
    const __nv_bfloat16* __restrict__ A, const __nv_bfloat16* __restrict__ B,
    int ldA, int ldB, int kIters,
    __nv_bfloat16* sA, __nv_bfloat16* sB, float c[4][4][4]) {
    const int tid = threadIdx.x;
    const int lane = tid & 31;
    const int warp = tid >> 5;
    const int wm = (warp >> 2) * 64;
    const int wn = (warp & 3) * 32;
    const int e0 = tid, e1 = tid + 256;

    const int a_row = lane & 15;
    const int a_k8 = (lane >> 4) * 8;
    const int bm8 = lane >> 3;
    const int b_row = (lane & 7) + (bm8 >> 1) * 8;
    const int b_k8 = (bm8 & 1) * 8;

    auto gA = [&](int e, int kt) {
        int r = e >> 2, cg = (e & 3) << 3;
        return *(const uint4*)(A + (size_t)r * ldA + kt * BK + cg);
    };
    auto gB = [&](int e, int kt) {
        int r = e >> 2, cg = (e & 3) << 3;
        return *(const uint4*)(B + (size_t)r * ldB + kt * BK + cg);
    };
    auto sWr = [&](__nv_bfloat16* s, int buf, int e, uint4 v) {
        int r = e >> 2, cg = (e & 3) << 3;
        *(uint4*)(s + buf * SBUF + r * SST + cg) = v;
    };

    sWr(sA, 0, e0, gA(e0, 0)); sWr(sA, 0, e1, gA(e1, 0));
    sWr(sB, 0, e0, gB(e0, 0)); sWr(sB, 0, e1, gB(e1, 0));
    __syncthreads();

    for (int kt = 0; kt < kIters; ++kt) {
        const int buf = kt & 1;
        uint4 pa0, pa1, pb0, pb1;
        const bool more = (kt + 1) < kIters;
        if (more) {
            pa0 = gA(e0, kt + 1); pa1 = gA(e1, kt + 1);
            pb0 = gB(e0, kt + 1); pb1 = gB(e1, kt + 1);
        }
        const __nv_bfloat16* cA = sA + buf * SBUF;
        const __nv_bfloat16* cB = sB + buf * SBUF;
#pragma unroll
        for (int ks = 0; ks < 2; ++ks) {
            uint32_t a[4][4], b[4][2];
#pragma unroll
            for (int mi = 0; mi < 4; ++mi) {
                uint32_t ad = smem_u32(cA + (wm + mi * 16 + a_row) * SST + ks * 16 + a_k8);
                ldmx4(a[mi][0], a[mi][1], a[mi][2], a[mi][3], ad);
            }
#pragma unroll
            for (int p = 0; p < 2; ++p) {
                uint32_t ad = smem_u32(cB + (wn + p * 16 + b_row) * SST + ks * 16 + b_k8);
                uint32_t r0, r1, r2, r3;
                ldmx4(r0, r1, r2, r3, ad);
                b[2 * p][0] = r0; b[2 * p][1] = r1;
                b[2 * p + 1][0] = r2; b[2 * p + 1][1] = r3;
            }
#pragma unroll
            for (int mi = 0; mi < 4; ++mi)
#pragma unroll
                for (int ni = 0; ni < 4; ++ni)
                    mma_bf16(c[mi][ni], a[mi], b[ni]);
        }
        if (more) {
            sWr(sA, buf ^ 1, e0, pa0); sWr(sA, buf ^ 1, e1, pa1);
            sWr(sB, buf ^ 1, e0, pb0); sWr(sB, buf ^ 1, e1, pb1);
        }
        __syncthreads();
    }
}

// ---------------------------------------------------------------------------
__global__ void k_convert_xs(const float4* __restrict__ xs) {
    size_t i = (size_t)blockIdx.x * blockDim.x + threadIdx.x;
    const size_t n4 = (size_t)NP * KD / 4;
    const size_t stride = (size_t)gridDim.x * blockDim.x;
    __nv_bfloat162* out = (__nv_bfloat162*)g_xsb;
    for (; i < n4; i += stride) {
        float4 v = xs[i];
        out[2 * i] = __floats2bfloat162_rn(v.x, v.y);
        out[2 * i + 1] = __floats2bfloat162_rn(v.z, v.w);
    }
}

__global__ void k_transpose_W(const float* __restrict__ W) {
    __shared__ float s[32][33];
    const int kb = blockIdx.y * 32, nb = blockIdx.x * 32;
    const int tx = threadIdx.x, ty = threadIdx.y;
#pragma unroll
    for (int r = 0; r < 32; r += 8)
        s[ty + r][tx] = W[(size_t)(kb + ty + r) * FD + nb + tx];
    __syncthreads();
#pragma unroll
    for (int r = 0; r < 32; r += 8)
        g_Wt[(size_t)(nb + ty + r) * KD + kb + tx] = __float2bfloat16(s[tx][ty + r]);
}

// GEMM1: X = xs @ W  -> g_Xb (bf16)
__global__ void __launch_bounds__(256, 1) k_gemm1() {
    __shared__ __align__(16) __nv_bfloat16 sA[2 * SBUF];
    __shared__ __align__(16) __nv_bfloat16 sB[2 * SBUF];
    float c[4][4][4];
#pragma unroll
    for (int i = 0; i < 4; i++)
#pragma unroll
        for (int j = 0; j < 4; j++)
#pragma unroll
            for (int k = 0; k < 4; k++) c[i][j][k] = 0.f;
    const int rowB = blockIdx.y * BM, colB = blockIdx.x * BN;
    gemm_mainloop(g_xsb + (size_t)rowB * KD, g_Wt + (size_t)colB * KD,
                  KD, KD, KD / BK, sA, sB, c);
    const int lane = threadIdx.x & 31, warp = threadIdx.x >> 5;
    const int wm = (warp >> 2) * 64, wn = (warp & 3) * 32;
#pragma unroll
    for (int mi = 0; mi < 4; mi++) {
        int r0 = rowB + wm + mi * 16 + (lane >> 2);
#pragma unroll
        for (int ni = 0; ni < 4; ni++) {
            int c0 = colB + wn + ni * 8 + (lane & 3) * 2;
            *(__nv_bfloat162*)(g_Xb + (size_t)r0 * FD + c0) =
                __floats2bfloat162_rn(c[mi][ni][0], c[mi][ni][1]);
            *(__nv_bfloat162*)(g_Xb + (size_t)(r0 + 8) * FD + c0) =
                __floats2bfloat162_rn(c[mi][ni][2], c[mi][ni][3]);
        }
    }
}

// Row stats: sq[i] = ||X_i||^2 (from the rounded X -> exact diagonal cancel),
// bv[i] = alpha_i * (2*y_i - 1)
__global__ void __launch_bounds__(256) k_rowstats(const int* __restrict__ ys,
                                                  const float* __restrict__ alphas) {
    const int i = blockIdx.x;
    const __nv_bfloat162* row = (const __nv_bfloat162*)(g_Xb + (size_t)i * FD);
    float s = 0.f;
    for (int t = threadIdx.x; t < FD / 2; t += 256) {
        __nv_bfloat162 v = row[t];
        float x = __bfloat162float(v.x), y = __bfloat162float(v.y);
        s += x * x + y * y;
    }
#pragma unroll
    for (int o = 16; o > 0; o >>= 1) s += __shfl_xor_sync(0xffffffffu, s, o);
    __shared__ float red[8];
    const int lane = threadIdx.x & 31, warp = threadIdx.x >> 5;
    if (lane == 0) red[warp] = s;
    __syncthreads();
    if (threadIdx.x == 0) {
        float t = 0.f;
        for (int w = 0; w < 8; w++) t += red[w];
        g_sq[i] = t;
        g_bv[i] = alphas[i] * (float)(2 * ys[i] - 1);
    }
}

// GEMM2 fused: S-tile = X_i @ X_j^T, then sum b_i b_j exp(-gamma*d2) in regs.
// Only upper-triangle tiles computed; off-diagonal weighted x2.
__global__ void __launch_bounds__(256, 1) k_gemm2() {
    const int ti = blockIdx.y, tj = blockIdx.x;
    const int bid = ti * 32 + tj;
    if (tj < ti) {
        if (threadIdx.x == 0) g_part[bid] = 0.f;
        return;
    }
    __shared__ __align__(16) __nv_bfloat16 sA[2 * SBUF];
    __shared__ __align__(16) __nv_bfloat16 sB[2 * SBUF];
    float c[4][4][4];
#pragma unroll
    for (int i = 0; i < 4; i++)
#pragma unroll
        for (int j = 0; j < 4; j++)
#pragma unroll
            for (int k = 0; k < 4; k++) c[i][j][k] = 0.f;
    gemm_mainloop(g_Xb + (size_t)ti * BM * FD, g_Xb + (size_t)tj * BN * FD,
                  FD, FD, FD / BK, sA, sB, c);
    const int lane = threadIdx.x & 31, warp = threadIdx.x >> 5;
    const int wm = (warp >> 2) * 64, wn = (warp & 3) * 32;
    float acc = 0.f;
#pragma unroll
    for (int mi = 0; mi < 4; mi++) {
        const int i0 = ti * BM + wm + mi * 16 + (lane >> 2);
        const int i1 = i0 + 8;
        const float sqi0 = g_sq[i0], sqi1 = g_sq[i1];
        const float bi0 = g_bv[i0], bi1 = g_bv[i1];
#pragma unroll
        for (int ni = 0; ni < 4; ni++) {
            const int j0 = tj * BN + wn + ni * 8 + (lane & 3) * 2;
            const int j1 = j0 + 1;
            const float sqj0 = g_sq[j0], sqj1 = g_sq[j1];
            const float bj0 = g_bv[j0], bj1 = g_bv[j1];
            acc += bi0 * bj0 * __expf(-GAMMA * fmaxf(sqi0 + sqj0 - 2.f * c[mi][ni][0], 0.f));
            acc += bi0 * bj1 * __expf(-GAMMA * fmaxf(sqi0 + sqj1 - 2.f * c[mi][ni][1], 0.f));
            acc += bi1 * bj0 * __expf(-GAMMA * fmaxf(sqi1 + sqj0 - 2.f * c[mi][ni][2], 0.f));
            acc += bi1 * bj1 * __expf(-GAMMA * fmaxf(sqi1 + sqj1 - 2.f * c[mi][ni][3], 0.f));
        }
    }
    if (ti != tj) acc *= 2.f;
#pragma unroll
    for (int o = 16; o > 0; o >>= 1) acc += __shfl_xor_sync(0xffffffffu, acc, o);
    __shared__ float red[8];
    if (lane == 0) red[warp] = acc;
    __syncthreads();
    if (threadIdx.x == 0) {
        float s = 0.f;
        for (int w = 0; w < 8; w++) s += red[w];
        g_part[bid] = s;
    }
}

// Final: out = 0.5 * sum(partials) - sum(alphas). Deterministic tree reduce.
__global__ void __launch_bounds__(256) k_final(const float* __restrict__ alphas,
                                               float* __restrict__ out) {
    float s1 = 0.f, s2 = 0.f;
    for (int t = threadIdx.x; t < 32 * 32; t += 256) s1 += g_part[t];
    for (int t = threadIdx.x; t < NP; t += 256) s2 += alphas[t];
#pragma unroll
    for (int o = 16; o > 0; o >>= 1) {
        s1 += __shfl_xor_sync(0xffffffffu, s1, o);
        s2 += __shfl_xor_sync(0xffffffffu, s2, o);
    }
    __shared__ float r1[8], r2[8];
    const int lane = threadIdx.x & 31, warp = threadIdx.x >> 5;
    if (lane == 0) { r1[warp] = s1; r2[warp] = s2; }
    __syncthreads();
    if (threadIdx.x == 0) {
        float a = 0.f, b = 0.f;
        for (int w = 0; w < 8; w++) { a += r1[w]; b += r2[w]; }
        out[0] = 0.5f * a - b;
    }
}

// ---------------------------------------------------------------------------
extern "C" void kernel_launch(void* const* d_in, const int* in_sizes, int n_in,
                              void* d_out, int out_size) {
    (void)in_sizes; (void)n_in; (void)out_size;
    const float* xs = (const float*)d_in[0];
    const float* W = (const float*)d_in[1];
    const int* ys = (const int*)d_in[2];
    const float* alphas = (const float*)d_in[3];
    float* out = (float*)d_out;

    k_convert_xs<<<2048, 256>>>((const float4*)xs);
    k_transpose_W<<<dim3(FD / 32, KD / 32), dim3(32, 8)>>>(W);
    k_gemm1<<<dim3(FD / BN, NP / BM), 256>>>();
    k_rowstats<<<NP, 256>>>(ys, alphas);
    k_gemm2<<<dim3(NP / BN, NP / BM), 256>>>();
    k_final<<<1, 256>>>(alphas, out);
}

// round 3
// speedup vs baseline: 1.7522x; 1.7522x over previous
#include <cuda_runtime.h>
#include <cuda_bf16.h>
#include <cstdint>

// Problem constants
constexpr int NP = 4096;   // data_length
constexpr int KD = 8192;   // T_IN * D_IN
constexpr int FD = 2048;   // F
constexpr float GAMMA = 1.0f / 2048.0f;

// GEMM tiling: 128x128 CTA tile, BK=64, 3-stage cp.async pipeline, SW128 smem
constexpr int BM = 128, BN = 128, BK = 64, STAGES = 3;
constexpr int AST = BM * 128;        // 16 KB per A stage (128B rows)
constexpr int BST = BN * 128;        // 16 KB per B stage
constexpr int STG = AST + BST;       // 32 KB per stage
constexpr int SMEM_BYTES = STAGES * STG;  // 96 KB

// Scratch (device globals; no runtime allocation)
__device__ __nv_bfloat16 g_xsb[(size_t)NP * KD];  // xs bf16 (64 MB)
__device__ __nv_bfloat16 g_Wt[(size_t)FD * KD];   // W^T bf16 (32 MB)
__device__ __nv_bfloat16 g_Xb[(size_t)NP * FD];   // X bf16 (16 MB)
__device__ float g_sq[NP];
__device__ float g_bv[NP];
__device__ float g_part[1024];

// ---------------------------------------------------------------------------
__device__ __forceinline__ uint32_t s2u(const void* p) {
    return (uint32_t)__cvta_generic_to_shared(p);
}
// SW128 swizzle: conflict-free ldmatrix on 128B rows
__device__ __forceinline__ uint32_t swz(uint32_t o) { return o ^ ((o >> 3) & 0x70); }
__device__ __forceinline__ void cpa16(uint32_t d, const void* g) {
    asm volatile("cp.async.cg.shared.global [%0], [%1], 16;\n" ::"r"(d), "l"(g));
}
__device__ __forceinline__ void cp_commit() {
    asm volatile("cp.async.commit_group;\n" ::: "memory");
}
__device__ __forceinline__ void ldmx4(uint32_t& r0, uint32_t& r1, uint32_t& r2,
                                      uint32_t& r3, uint32_t a) {
    asm volatile("ldmatrix.sync.aligned.m8n8.x4.shared.b16 {%0,%1,%2,%3}, [%4];\n"
                 : "=r"(r0), "=r"(r1), "=r"(r2), "=r"(r3) : "r"(a));
}
__device__ __forceinline__ void mma_bf16(float c[4], const uint32_t a[4],
                                         const uint32_t b[2]) {
    asm volatile(
        "mma.sync.aligned.m16n8k16.row.col.f32.bf16.bf16.f32 "
        "{%0,%1,%2,%3}, {%4,%5,%6,%7}, {%8,%9}, {%0,%1,%2,%3};\n"
        : "+f"(c[0]), "+f"(c[1]), "+f"(c[2]), "+f"(c[3])
        : "r"(a[0]), "r"(a[1]), "r"(a[2]), "r"(a[3]), "r"(b[0]), "r"(b[1]));
}

// Load one BK=64 stage of A[128] and B[128] tiles into swizzled smem.
__device__ __forceinline__ void load_stage(const __nv_bfloat16* A,
                                           const __nv_bfloat16* B, size_t ldA,
                                           size_t ldB, uint32_t sb, int kt) {
    const int tid = threadIdx.x;
    const uint32_t sa = sb + (kt % STAGES) * STG;
    const uint32_t sbm = sa + AST;
    const __nv_bfloat16* As = A + (size_t)kt * BK;
    const __nv_bfloat16* Bs = B + (size_t)kt * BK;
#pragma unroll
    for (int t = 0; t < 4; t++) {  // 1024 16B chunks / 256 threads
        int ch = tid + t * 256, r = ch >> 3, c = ch & 7;
        cpa16(sa + swz(r * 128 + c * 16), As + (size_t)r * ldA + c * 8);
    }
#pragma unroll
    for (int t = 0; t < 4; t++) {
        int ch = tid + t * 256, r = ch >> 3, c = ch & 7;
        cpa16(sbm + swz(r * 128 + c * 16), Bs + (size_t)r * ldB + c * 8);
    }
}

// NT GEMM mainloop: A [m][k] row-major, B [n][k] row-major, both bf16.
// 256 threads, 8 warps 2(m)x4(n), warp tile 64x32, accum in regs c[4][4][4].
__device__ __forceinline__ void gemm_mainloop(const __nv_bfloat16* __restrict__ A,
                                              const __nv_bfloat16* __restrict__ B,
                                              size_t ldA, size_t ldB, int kIters,
                                              float c[4][4][4]) {
    extern __shared__ char smem[];
    const uint32_t sb = s2u(smem);
    const int tid = threadIdx.x, lane = tid & 31, warp = tid >> 5;
    const int wm = (warp >> 2) * 64, wn = (warp & 3) * 32;
    const int ra = lane & 15, klo = lane >> 4;          // A frag addressing
    const int bm8 = lane >> 3;                          // B frag addressing
    const int brow = (lane & 7) + (bm8 >> 1) * 8;
    const int bk = bm8 & 1;

    load_stage(A, B, ldA, ldB, sb, 0); cp_commit();
    load_stage(A, B, ldA, ldB, sb, 1); cp_commit();
    load_stage(A, B, ldA, ldB, sb, 2); cp_commit();

    for (int kt = 0; kt < kIters; ++kt) {
        asm volatile("cp.async.wait_group 2;\n" ::: "memory");
        __syncthreads();
        const uint32_t sA = sb + (kt % STAGES) * STG;
        const uint32_t sB = sA + AST;
#pragma unroll
        for (int ks = 0; ks < 4; ++ks) {  // 4 x k16 per stage
            uint32_t a[4][4], b[4][2];
#pragma unroll
            for (int mi = 0; mi < 4; ++mi) {
                uint32_t ad = sA + swz((wm + mi * 16 + ra) * 128 + (klo + 2 * ks) * 16);
                ldmx4(a[mi][0], a[mi][1], a[mi][2], a[mi][3], ad);
            }
#pragma unroll
            for (int p = 0; p < 2; ++p) {
                uint32_t ad = sB + swz((wn + p * 16 + brow) * 128 + (bk + 2 * ks) * 16);
                uint32_t r0, r1, r2, r3;
                ldmx4(r0, r1, r2, r3, ad);
                b[2 * p][0] = r0; b[2 * p][1] = r1;
                b[2 * p + 1][0] = r2; b[2 * p + 1][1] = r3;
            }
#pragma unroll
            for (int mi = 0; mi < 4; ++mi)
#pragma unroll
                for (int ni = 0; ni < 4; ++ni)
                    mma_bf16(c[mi][ni], a[mi], b[ni]);
        }
        __syncthreads();
        if (kt + STAGES < kIters) load_stage(A, B, ldA, ldB, sb, kt + STAGES);
        cp_commit();  // keep group count constant (possibly empty group)
    }
}

// ---------------------------------------------------------------------------
__global__ void k_convert_xs(const float4* __restrict__ xs) {
    size_t i = (size_t)blockIdx.x * blockDim.x + threadIdx.x;
    const size_t n4 = (size_t)NP * KD / 4;
    const size_t stride = (size_t)gridDim.x * blockDim.x;
    __nv_bfloat162* out = (__nv_bfloat162*)g_xsb;
    for (; i < n4; i += stride) {
        float4 v = xs[i];
        out[2 * i] = __floats2bfloat162_rn(v.x, v.y);
        out[2 * i + 1] = __floats2bfloat162_rn(v.z, v.w);
    }
}

__global__ void k_transpose_W(const float* __restrict__ W) {
    __shared__ float s[32][33];
    const int kb = blockIdx.y * 32, nb = blockIdx.x * 32;
    const int tx = threadIdx.x, ty = threadIdx.y;
#pragma unroll
    for (int r = 0; r < 32; r += 8)
        s[ty + r][tx] = W[(size_t)(kb + ty + r) * FD + nb + tx];
    __syncthreads();
#pragma unroll
    for (int r = 0; r < 32; r += 8)
        g_Wt[(size_t)(nb + ty + r) * KD + kb + tx] = __float2bfloat16(s[tx][ty + r]);
}

// GEMM1: X = xs @ W -> g_Xb (bf16)
__global__ void __launch_bounds__(256, 2) k_gemm1() {
    float c[4][4][4];
#pragma unroll
    for (int i = 0; i < 4; i++)
#pragma unroll
        for (int j = 0; j < 4; j++)
#pragma unroll
            for (int k = 0; k < 4; k++) c[i][j][k] = 0.f;
    const int rowB = blockIdx.y * BM, colB = blockIdx.x * BN;
    gemm_mainloop(g_xsb + (size_t)rowB * KD, g_Wt + (size_t)colB * KD, KD, KD,
                  KD / BK, c);
    const int lane = threadIdx.x & 31, warp = threadIdx.x >> 5;
    const int wm = (warp >> 2) * 64, wn = (warp & 3) * 32;
#pragma unroll
    for (int mi = 0; mi < 4; mi++) {
        int r0 = rowB + wm + mi * 16 + (lane >> 2);
#pragma unroll
        for (int ni = 0; ni < 4; ni++) {
            int c0 = colB + wn + ni * 8 + (lane & 3) * 2;
            *(__nv_bfloat162*)(g_Xb + (size_t)r0 * FD + c0) =
                __floats2bfloat162_rn(c[mi][ni][0], c[mi][ni][1]);
            *(__nv_bfloat162*)(g_Xb + (size_t)(r0 + 8) * FD + c0) =
                __floats2bfloat162_rn(c[mi][ni][2], c[mi][ni][3]);
        }
    }
}

// Row stats (warp per row): sq[i] = ||X_i||^2 from ROUNDED X (exact diag cancel),
// bv[i] = alpha_i * (2*y_i - 1)
__global__ void __launch_bounds__(256) k_rowstats(const int* __restrict__ ys,
                                                  const float* __restrict__ alphas) {
    const int row = (blockIdx.x * 256 + threadIdx.x) >> 5;
    const int lane = threadIdx.x & 31;
    const uint4* p = (const uint4*)(g_Xb + (size_t)row * FD);
    float s = 0.f;
#pragma unroll
    for (int it = 0; it < 8; it++) {  // 2048 bf16 = 256 uint4 = 32 lanes x 8
        uint4 v = p[it * 32 + lane];
        const __nv_bfloat162* h = (const __nv_bfloat162*)&v;
#pragma unroll
        for (int q = 0; q < 4; q++) {
            float2 f = __bfloat1622float2(h[q]);
            s += f.x * f.x + f.y * f.y;
        }
    }
#pragma unroll
    for (int o = 16; o > 0; o >>= 1) s += __shfl_xor_sync(0xffffffffu, s, o);
    if (lane == 0) {
        g_sq[row] = s;
        g_bv[row] = alphas[row] * (float)(2 * ys[row] - 1);
    }
}

// GEMM2 fused: S-tile = X_i @ X_j^T in regs, then sum b_i b_j exp(-gamma*d2).
// Upper-triangle tiles only; off-diagonal tiles weighted x2.
__global__ void __launch_bounds__(256, 2) k_gemm2() {
    const int ti = blockIdx.y, tj = blockIdx.x;
    const int bid = ti * 32 + tj;
    if (tj < ti) {
        if (threadIdx.x == 0) g_part[bid] = 0.f;
        return;
    }
    float c[4][4][4];
#pragma unroll
    for (int i = 0; i < 4; i++)
#pragma unroll
        for (int j = 0; j < 4; j++)
#pragma unroll
            for (int k = 0; k < 4; k++) c[i][j][k] = 0.f;
    gemm_mainloop(g_Xb + (size_t)ti * BM * FD, g_Xb + (size_t)tj * BN * FD, FD, FD,
                  FD / BK, c);
    const int lane = threadIdx.x & 31, warp = threadIdx.x >> 5;
    const int wm = (warp >> 2) * 64, wn = (warp & 3) * 32;
    float acc = 0.f;
#pragma unroll
    for (int mi = 0; mi < 4; mi++) {
        const int i0 = ti * BM + wm + mi * 16 + (lane >> 2);
        const int i1 = i0 + 8;
        const float sqi0 = g_sq[i0], sqi1 = g_sq[i1];
        const float bi0 = g_bv[i0], bi1 = g_bv[i1];
#pragma unroll
        for (int ni = 0; ni < 4; ni++) {
            const int j0 = tj * BN + wn + ni * 8 + (lane & 3) * 2;
            const int j1 = j0 + 1;
            const float sqj0 = g_sq[j0], sqj1 = g_sq[j1];
            const float bj0 = g_bv[j0], bj1 = g_bv[j1];
            acc += bi0 * bj0 * __expf(-GAMMA * fmaxf(sqi0 + sqj0 - 2.f * c[mi][ni][0], 0.f));
            acc += bi0 * bj1 * __expf(-GAMMA * fmaxf(sqi0 + sqj1 - 2.f * c[mi][ni][1], 0.f));
            acc += bi1 * bj0 * __expf(-GAMMA * fmaxf(sqi1 + sqj0 - 2.f * c[mi][ni][2], 0.f));
            acc += bi1 * bj1 * __expf(-GAMMA * fmaxf(sqi1 + sqj1 - 2.f * c[mi][ni][3], 0.f));
        }
    }
    if (ti != tj) acc *= 2.f;
#pragma unroll
    for (int o = 16; o > 0; o >>= 1) acc += __shfl_xor_sync(0xffffffffu, acc, o);
    extern __shared__ char smem[];
    float* red = (float*)smem;  // mainloop done; smem reusable
    if (lane == 0) red[warp] = acc;
    __syncthreads();
    if (threadIdx.x == 0) {
        float s = 0.f;
        for (int q = 0; q < 8; q++) s += red[q];
        g_part[bid] = s;
    }
}

// Final: out = 0.5 * sum(partials) - sum(alphas). Deterministic tree reduce.
__global__ void __launch_bounds__(256) k_final(const float* __restrict__ alphas,
                                               float* __restrict__ out) {
    float s1 = 0.f, s2 = 0.f;
    for (int t = threadIdx.x; t < 1024; t += 256) s1 += g_part[t];
    for (int t = threadIdx.x; t < NP; t += 256) s2 += alphas[t];
#pragma unroll
    for (int o = 16; o > 0; o >>= 1) {
        s1 += __shfl_xor_sync(0xffffffffu, s1, o);
        s2 += __shfl_xor_sync(0xffffffffu, s2, o);
    }
    __shared__ float r1[8], r2[8];
    const int lane = threadIdx.x & 31, warp = threadIdx.x >> 5;
    if (lane == 0) { r1[warp] = s1; r2[warp] = s2; }
    __syncthreads();
    if (threadIdx.x == 0) {
        float a = 0.f, b = 0.f;
        for (int q = 0; q < 8; q++) { a += r1[q]; b += r2[q]; }
        out[0] = 0.5f * a - b;
    }
}

// ---------------------------------------------------------------------------
extern "C" void kernel_launch(void* const* d_in, const int* in_sizes, int n_in,
                              void* d_out, int out_size) {
    (void)in_sizes; (void)n_in; (void)out_size;
    const float* xs = (const float*)d_in[0];
    const float* W = (const float*)d_in[1];
    const int* ys = (const int*)d_in[2];
    const float* alphas = (const float*)d_in[3];
    float* out = (float*)d_out;

    cudaFuncSetAttribute(k_gemm1, cudaFuncAttributeMaxDynamicSharedMemorySize,
                         SMEM_BYTES);
    cudaFuncSetAttribute(k_gemm2, cudaFuncAttributeMaxDynamicSharedMemorySize,
                         SMEM_BYTES);

    k_convert_xs<<<2048, 256>>>((const float4*)xs);
    k_transpose_W<<<dim3(FD / 32, KD / 32), dim3(32, 8)>>>(W);
    k_gemm1<<<dim3(FD / BN, NP / BM), 256, SMEM_BYTES>>>();
    k_rowstats<<<NP / 8, 256>>>(ys, alphas);
    k_gemm2<<<dim3(NP / BN, NP / BM), 256, SMEM_BYTES>>>();
    k_final<<<1, 256>>>(alphas, out);
}

// round 5
// speedup vs baseline: 1.7810x; 1.0164x over previous
#include <cuda_runtime.h>
#include <cuda_bf16.h>
#include <cstdint>

// Problem constants
constexpr int NP = 4096;   // data_length
constexpr int KD = 8192;   // T_IN * D_IN
constexpr int FD = 2048;   // F
constexpr float GAMMA = 1.0f / 2048.0f;

constexpr int BK = 64;

// Scratch (device globals; no runtime allocation)
__device__ __nv_bfloat16 g_xsb[(size_t)NP * KD];  // xs bf16 (64 MB)
__device__ __nv_bfloat16 g_Wt[(size_t)FD * KD];   // W^T bf16 (32 MB)
__device__ __nv_bfloat16 g_Xb[(size_t)NP * FD];   // X bf16 (16 MB)
__device__ float g_sq[NP];
__device__ float g_bv[NP];
__device__ float g_part[1024];

// ---------------------------------------------------------------------------
__device__ __forceinline__ uint32_t s2u(const void* p) {
    return (uint32_t)__cvta_generic_to_shared(p);
}
__device__ __forceinline__ uint32_t swz(uint32_t o) { return o ^ ((o >> 3) & 0x70); }
__device__ __forceinline__ void cpa16(uint32_t d, const void* g) {
    asm volatile("cp.async.cg.shared.global [%0], [%1], 16;\n" ::"r"(d), "l"(g));
}
__device__ __forceinline__ void cp_commit() {
    asm volatile("cp.async.commit_group;\n" ::: "memory");
}
__device__ __forceinline__ void ldmx4(uint32_t& r0, uint32_t& r1, uint32_t& r2,
                                      uint32_t& r3, uint32_t a) {
    asm volatile("ldmatrix.sync.aligned.m8n8.x4.shared.b16 {%0,%1,%2,%3}, [%4];\n"
                 : "=r"(r0), "=r"(r1), "=r"(r2), "=r"(r3) : "r"(a));
}
__device__ __forceinline__ void mma_bf16(float c[4], const uint32_t a[4],
                                         const uint32_t b[2]) {
    asm volatile(
        "mma.sync.aligned.m16n8k16.row.col.f32.bf16.bf16.f32 "
        "{%0,%1,%2,%3}, {%4,%5,%6,%7}, {%8,%9}, {%0,%1,%2,%3};\n"
        : "+f"(c[0]), "+f"(c[1]), "+f"(c[2]), "+f"(c[3])
        : "r"(a[0]), "r"(a[1]), "r"(a[2]), "r"(a[3]), "r"(b[0]), "r"(b[1]));
}

// Load one BK=64 stage: A[128 rows] + B[BNT rows], 128B swizzled rows.
template <int BNT, int NSTG>
__device__ __forceinline__ void load_stage(const __nv_bfloat16* A,
                                           const __nv_bfloat16* B, size_t ldA,
                                           size_t ldB, uint32_t sb, int kt) {
    constexpr int AST = 128 * 128;
    constexpr int STG = AST + BNT * 128;
    const int tid = threadIdx.x;
    const uint32_t sa = sb + (kt % NSTG) * STG;
    const uint32_t sbm = sa + AST;
    const __nv_bfloat16* As = A + (size_t)kt * BK;
    const __nv_bfloat16* Bs = B + (size_t)kt * BK;
#pragma unroll
    for (int t = 0; t < 4; t++) {
        int ch = tid + t * 256, r = ch >> 3, c = ch & 7;
        cpa16(sa + swz(r * 128 + c * 16), As + (size_t)r * ldA + c * 8);
    }
#pragma unroll
    for (int t = 0; t < BNT / 32; t++) {
        int ch = tid + t * 256, r = ch >> 3, c = ch & 7;
        cpa16(sbm + swz(r * 128 + c * 16), Bs + (size_t)r * ldB + c * 8);
    }
}

// NT GEMM mainloop: A [m][k], B [n][k] row-major bf16. 256 threads, 8 warps
// (2m x 4n), warp tile 64 x (WNI*8). Accum c[4][WNI][4].
template <int BNT, int WNI, int NSTG>
__device__ __forceinline__ void gemm_mainloop(const __nv_bfloat16* __restrict__ A,
                                              const __nv_bfloat16* __restrict__ B,
                                              size_t ldA, size_t ldB, int kIters,
                                              float c[4][WNI][4]) {
    constexpr int AST = 128 * 128;
    constexpr int STG = AST + BNT * 128;
    extern __shared__ char smem[];
    const uint32_t sb = s2u(smem);
    const int tid = threadIdx.x, lane = tid & 31, warp = tid >> 5;
    const int wm = (warp >> 2) * 64, wn = (warp & 3) * (WNI * 8);
    const int ra = lane & 15, klo = lane >> 4;
    const int bm8 = lane >> 3;
    const int brow = (lane & 7) + (bm8 >> 1) * 8;
    const int bk = bm8 & 1;

#pragma unroll
    for (int s = 0; s < NSTG; s++) {
        load_stage<BNT, NSTG>(A, B, ldA, ldB, sb, s);
        cp_commit();
    }

    for (int kt = 0; kt < kIters; ++kt) {
        asm volatile("cp.async.wait_group %0;\n" ::"n"(NSTG - 1) : "memory");
        __syncthreads();
        const uint32_t sA = sb + (kt % NSTG) * STG;
        const uint32_t sB = sA + AST;
#pragma unroll
        for (int ks = 0; ks < 4; ++ks) {  // 4 x k16 per BK=64 stage
            uint32_t a[4][4], b[WNI][2];
#pragma unroll
            for (int mi = 0; mi < 4; ++mi) {
                uint32_t ad = sA + swz((wm + mi * 16 + ra) * 128 + (klo + 2 * ks) * 16);
                ldmx4(a[mi][0], a[mi][1], a[mi][2], a[mi][3], ad);
            }
#pragma unroll
            for (int p = 0; p < WNI / 2; ++p) {
                uint32_t ad = sB + swz((wn + p * 16 + brow) * 128 + (bk + 2 * ks) * 16);
                uint32_t r0, r1, r2, r3;
                ldmx4(r0, r1, r2, r3, ad);
                b[2 * p][0] = r0; b[2 * p][1] = r1;
                b[2 * p + 1][0] = r2; b[2 * p + 1][1] = r3;
            }
#pragma unroll
            for (int mi = 0; mi < 4; ++mi)
#pragma unroll
                for (int ni = 0; ni < WNI; ++ni)
                    mma_bf16(c[mi][ni], a[mi], b[ni]);
        }
        __syncthreads();
        if (kt + NSTG < kIters) load_stage<BNT, NSTG>(A, B, ldA, ldB, sb, kt + NSTG);
        cp_commit();  // constant group count
    }
}

// ---------------------------------------------------------------------------
// Fused pre-pass: W transpose (blocks [0, 8192)), xs fp32->bf16 (next 2048),
// bv + sq-zero (last 32). One launch, all HBM-bound work overlapped.
constexpr int TW_BLK = (FD / 32) * (KD / 64);  // 8192
constexpr int CV_BLK = 2048;
__global__ void __launch_bounds__(256) k_pre(const float* __restrict__ xs,
                                             const float* __restrict__ W,
                                             const int* __restrict__ ys,
                                             const float* __restrict__ alphas) {
    const int bid = blockIdx.x;
    const int tid = threadIdx.x;
    if (bid < TW_BLK) {  // transpose 64(k) x 32(n) tile of W
        __shared__ float s[64][33];
        const int nb = (bid & 63) * 32, kb = (bid >> 6) * 64;
        const int tx = tid & 31, ty = tid >> 5;
#pragma unroll
        for (int r = 0; r < 64; r += 8)
            s[ty + r][tx] = W[(size_t)(kb + ty + r) * FD + nb + tx];
        __syncthreads();
#pragma unroll
        for (int rr = 0; rr < 4; rr++) {  // warp ty writes rows ty+8*rr: 128B/warp
            int n = ty + rr * 8;
            __nv_bfloat162 v = __floats2bfloat162_rn(s[2 * tx][n], s[2 * tx + 1][n]);
            *(__nv_bfloat162*)(g_Wt + (size_t)(nb + n) * KD + kb + 2 * tx) = v;
        }
    } else if (bid < TW_BLK + CV_BLK) {  // convert xs
        size_t i = (size_t)(bid - TW_BLK) * 256 + tid;
        const size_t n4 = (size_t)NP * KD / 4;
        const size_t stride = (size_t)CV_BLK * 256;
        __nv_bfloat162* out = (__nv_bfloat162*)g_xsb;
        const float4* in = (const float4*)xs;
        for (; i < n4; i += stride) {
            float4 v = in[i];
            out[2 * i] = __floats2bfloat162_rn(v.x, v.y);
            out[2 * i + 1] = __floats2bfloat162_rn(v.z, v.w);
        }
    } else {  // bv + sq init
        const int b = bid - TW_BLK - CV_BLK;  // 0..31
        const int i = (b & 15) * 256 + tid;
        if (b < 16) g_bv[i] = alphas[i] * (float)(2 * ys[i] - 1);
        else g_sq[i] = 0.f;
    }
}

// GEMM1: X = xs @ W -> g_Xb bf16; row-norm partials fused (squares of the
// ROUNDED bf16 values -> exact diagonal cancellation in GEMM2).
__global__ void __launch_bounds__(256, 1) k_gemm1() {
    float c[4][8][4];
#pragma unroll
    for (int i = 0; i < 4; i++)
#pragma unroll
        for (int j = 0; j < 8; j++)
#pragma unroll
            for (int k = 0; k < 4; k++) c[i][j][k] = 0.f;
    const int rowB = blockIdx.y * 128, colB = blockIdx.x * 256;
    gemm_mainloop<256, 8, 4>(g_xsb + (size_t)rowB * KD, g_Wt + (size_t)colB * KD,
                             KD, KD, KD / BK, c);
    const int lane = threadIdx.x & 31, warp = threadIdx.x >> 5;
    const int wm = (warp >> 2) * 64, wn = (warp & 3) * 64;
#pragma unroll
    for (int mi = 0; mi < 4; mi++) {
        const int r0 = rowB + wm + mi * 16 + (lane >> 2);
        float ss0 = 0.f, ss1 = 0.f;
#pragma unroll
        for (int ni = 0; ni < 8; ni++) {
            int c0 = colB + wn + ni * 8 + (lane & 3) * 2;
            __nv_bfloat162 v0 = __floats2bfloat162_rn(c[mi][ni][0], c[mi][ni][1]);
            __nv_bfloat162 v1 = __floats2bfloat162_rn(c[mi][ni][2], c[mi][ni][3]);
            *(__nv_bfloat162*)(g_Xb + (size_t)r0 * FD + c0) = v0;
            *(__nv_bfloat162*)(g_Xb + (size_t)(r0 + 8) * FD + c0) = v1;
            float2 f0 = __bfloat1622float2(v0), f1 = __bfloat1622float2(v1);
            ss0 += f0.x * f0.x + f0.y * f0.y;
            ss1 += f1.x * f1.x + f1.y * f1.y;
        }
        // reduce across the 4 lanes sharing each row (lane quads), then atomic
        ss0 += __shfl_xor_sync(0xffffffffu, ss0, 1);
        ss0 += __shfl_xor_sync(0xffffffffu, ss0, 2);
        ss1 += __shfl_xor_sync(0xffffffffu, ss1, 1);
        ss1 += __shfl_xor_sync(0xffffffffu, ss1, 2);
        if ((lane & 3) == 0) {
            atomicAdd(&g_sq[r0], ss0);
            atomicAdd(&g_sq[r0 + 8], ss1);
        }
    }
}

// GEMM2 fused: S-tile = X_i @ X_j^T in regs, then sum b_i b_j exp(-gamma*d2).
// Upper-triangle tiles only; off-diagonal tiles weighted x2.
__global__ void __launch_bounds__(256, 2) k_gemm2() {
    const int ti = blockIdx.y, tj = blockIdx.x;
    const int bid = ti * 32 + tj;
    if (tj < ti) {
        if (threadIdx.x == 0) g_part[bid] = 0.f;
        return;
    }
    float c[4][4][4];
#pragma unroll
    for (int i = 0; i < 4; i++)
#pragma unroll
        for (int j = 0; j < 4; j++)
#pragma unroll
            for (int k = 0; k < 4; k++) c[i][j][k] = 0.f;
    gemm_mainloop<128, 4, 3>(g_Xb + (size_t)ti * 128 * FD,
                             g_Xb + (size_t)tj * 128 * FD, FD, FD, FD / BK, c);
    const int lane = threadIdx.x & 31, warp = threadIdx.x >> 5;
    const int wm = (warp >> 2) * 64, wn = (warp & 3) * 32;
    float acc = 0.f;
#pragma unroll
    for (int mi = 0; mi < 4; mi++) {
        const int i0 = ti * 128 + wm + mi * 16 + (lane >> 2);
        const int i1 = i0 + 8;
        const float sqi0 = g_sq[i0], sqi1 = g_sq[i1];
        const float bi0 = g_bv[i0], bi1 = g_bv[i1];
#pragma unroll
        for (int ni = 0; ni < 4; ni++) {
            const int j0 = tj * 128 + wn + ni * 8 + (lane & 3) * 2;
            const int j1 = j0 + 1;
            const float sqj0 = g_sq[j0], sqj1 = g_sq[j1];
            const float bj0 = g_bv[j0], bj1 = g_bv[j1];
            acc += bi0 * bj0 * __expf(-GAMMA * fmaxf(sqi0 + sqj0 - 2.f * c[mi][ni][0], 0.f));
            acc += bi0 * bj1 * __expf(-GAMMA * fmaxf(sqi0 + sqj1 - 2.f * c[mi][ni][1], 0.f));
            acc += bi1 * bj0 * __expf(-GAMMA * fmaxf(sqi1 + sqj0 - 2.f * c[mi][ni][2], 0.f));
            acc += bi1 * bj1 * __expf(-GAMMA * fmaxf(sqi1 + sqj1 - 2.f * c[mi][ni][3], 0.f));
        }
    }
    if (ti != tj) acc *= 2.f;
#pragma unroll
    for (int o = 16; o > 0; o >>= 1) acc += __shfl_xor_sync(0xffffffffu, acc, o);
    extern __shared__ char smem[];
    float* red = (float*)smem;
    if (lane == 0) red[warp] = acc;
    __syncthreads();
    if (threadIdx.x == 0) {
        float s = 0.f;
        for (int q = 0; q < 8; q++) s += red[q];
        g_part[bid] = s;
    }
}

// Final: out = 0.5 * sum(partials) - sum(alphas). Deterministic tree reduce.
__global__ void __launch_bounds__(256) k_final(const float* __restrict__ alphas,
                                               float* __restrict__ out) {
    float s1 = 0.f, s2 = 0.f;
    for (int t = threadIdx.x; t < 1024; t += 256) s1 += g_part[t];
    for (int t = threadIdx.x; t < NP; t += 256) s2 += alphas[t];
#pragma unroll
    for (int o = 16; o > 0; o >>= 1) {
        s1 += __shfl_xor_sync(0xffffffffu, s1, o);
        s2 += __shfl_xor_sync(0xffffffffu, s2, o);
    }
    __shared__ float r1[8], r2[8];
    const int lane = threadIdx.x & 31, warp = threadIdx.x >> 5;
    if (lane == 0) { r1[warp] = s1; r2[warp] = s2; }
    __syncthreads();
    if (threadIdx.x == 0) {
        float a = 0.f, b = 0.f;
        for (int q = 0; q < 8; q++) { a += r1[q]; b += r2[q]; }
        out[0] = 0.5f * a - b;
    }
}

// ---------------------------------------------------------------------------
constexpr int SMEM_G1 = 4 * (128 * 128 + 256 * 128);  // 192 KB
constexpr int SMEM_G2 = 3 * (128 * 128 + 128 * 128);  // 96 KB

extern "C" void kernel_launch(void* const* d_in, const int* in_sizes, int n_in,
                              void* d_out, int out_size) {
    (void)in_sizes; (void)n_in; (void)out_size;
    const float* xs = (const float*)d_in[0];
    const float* W = (const float*)d_in[1];
    const int* ys = (const int*)d_in[2];
    const float* alphas = (const float*)d_in[3];
    float* out = (float*)d_out;

    cudaFuncSetAttribute(k_gemm1, cudaFuncAttributeMaxDynamicSharedMemorySize,
                         SMEM_G1);
    cudaFuncSetAttribute(k_gemm2, cudaFuncAttributeMaxDynamicSharedMemorySize,
                         SMEM_G2);

    k_pre<<<TW_BLK + CV_BLK + 32, 256>>>(xs, W, ys, alphas);
    k_gemm1<<<dim3(FD / 256, NP / 128), 256, SMEM_G1>>>();
    k_gemm2<<<dim3(NP / 128, NP / 128), 256, SMEM_G2>>>();
    k_final<<<1, 256>>>(alphas, out);
}

// round 6
// speedup vs baseline: 1.7887x; 1.0043x over previous
#include <cuda_runtime.h>
#include <cuda_bf16.h>
#include <cstdint>

// Problem constants
constexpr int NP = 4096;   // data_length
constexpr int KD = 8192;   // T_IN * D_IN
constexpr int FD = 2048;   // F
constexpr float GAMMA = 1.0f / 2048.0f;

constexpr int BK = 64;
constexpr int KSPLIT = 4;             // GEMM1 split-K factor
constexpr int KQ = KD / KSPLIT;       // 2048 per quarter

// Scratch (device globals; no runtime allocation)
__device__ __nv_bfloat16 g_xsb[(size_t)NP * KD];  // xs bf16 (64 MB)
__device__ __nv_bfloat16 g_Wt[(size_t)FD * KD];   // W^T bf16 (32 MB)
__device__ float g_Xf[(size_t)NP * FD];           // X fp32 accum (32 MB)
__device__ __nv_bfloat16 g_Xb[(size_t)NP * FD];   // X bf16 (16 MB)
__device__ float g_sq[NP];
__device__ float g_bv[NP];

// ---------------------------------------------------------------------------
__device__ __forceinline__ uint32_t s2u(const void* p) {
    return (uint32_t)__cvta_generic_to_shared(p);
}
__device__ __forceinline__ uint32_t swz(uint32_t o) { return o ^ ((o >> 3) & 0x70); }
__device__ __forceinline__ void cpa16(uint32_t d, const void* g) {
    asm volatile("cp.async.cg.shared.global [%0], [%1], 16;\n" ::"r"(d), "l"(g));
}
__device__ __forceinline__ void cp_commit() {
    asm volatile("cp.async.commit_group;\n" ::: "memory");
}
__device__ __forceinline__ void ldmx4(uint32_t& r0, uint32_t& r1, uint32_t& r2,
                                      uint32_t& r3, uint32_t a) {
    asm volatile("ldmatrix.sync.aligned.m8n8.x4.shared.b16 {%0,%1,%2,%3}, [%4];\n"
                 : "=r"(r0), "=r"(r1), "=r"(r2), "=r"(r3) : "r"(a));
}
__device__ __forceinline__ void mma_bf16(float c[4], const uint32_t a[4],
                                         const uint32_t b[2]) {
    asm volatile(
        "mma.sync.aligned.m16n8k16.row.col.f32.bf16.bf16.f32 "
        "{%0,%1,%2,%3}, {%4,%5,%6,%7}, {%8,%9}, {%0,%1,%2,%3};\n"
        : "+f"(c[0]), "+f"(c[1]), "+f"(c[2]), "+f"(c[3])
        : "r"(a[0]), "r"(a[1]), "r"(a[2]), "r"(a[3]), "r"(b[0]), "r"(b[1]));
}

// Load one BK=64 stage: A[128 rows] + B[BNT rows], 128B swizzled rows.
template <int BNT, int NSTG>
__device__ __forceinline__ void load_stage(const __nv_bfloat16* A,
                                           const __nv_bfloat16* B, size_t ldA,
                                           size_t ldB, uint32_t sb, int kt) {
    constexpr int AST = 128 * 128;
    constexpr int STG = AST + BNT * 128;
    const int tid = threadIdx.x;
    const uint32_t sa = sb + (kt % NSTG) * STG;
    const uint32_t sbm = sa + AST;
    const __nv_bfloat16* As = A + (size_t)kt * BK;
    const __nv_bfloat16* Bs = B + (size_t)kt * BK;
#pragma unroll
    for (int t = 0; t < 4; t++) {
        int ch = tid + t * 256, r = ch >> 3, c = ch & 7;
        cpa16(sa + swz(r * 128 + c * 16), As + (size_t)r * ldA + c * 8);
    }
#pragma unroll
    for (int t = 0; t < BNT / 32; t++) {
        int ch = tid + t * 256, r = ch >> 3, c = ch & 7;
        cpa16(sbm + swz(r * 128 + c * 16), Bs + (size_t)r * ldB + c * 8);
    }
}

// NT GEMM mainloop: A [m][k], B [n][k] row-major bf16. 256 threads, 8 warps
// (2m x 4n), warp tile 64 x (WNI*8). Accum c[4][WNI][4].
template <int BNT, int WNI, int NSTG>
__device__ __forceinline__ void gemm_mainloop(const __nv_bfloat16* __restrict__ A,
                                              const __nv_bfloat16* __restrict__ B,
                                              size_t ldA, size_t ldB, int kIters,
                                              float c[4][WNI][4]) {
    constexpr int AST = 128 * 128;
    constexpr int STG = AST + BNT * 128;
    extern __shared__ char smem[];
    const uint32_t sb = s2u(smem);
    const int tid = threadIdx.x, lane = tid & 31, warp = tid >> 5;
    const int wm = (warp >> 2) * 64, wn = (warp & 3) * (WNI * 8);
    const int ra = lane & 15, klo = lane >> 4;
    const int bm8 = lane >> 3;
    const int brow = (lane & 7) + (bm8 >> 1) * 8;
    const int bk = bm8 & 1;

#pragma unroll
    for (int s = 0; s < NSTG; s++) {
        load_stage<BNT, NSTG>(A, B, ldA, ldB, sb, s);
        cp_commit();
    }

    for (int kt = 0; kt < kIters; ++kt) {
        asm volatile("cp.async.wait_group %0;\n" ::"n"(NSTG - 1) : "memory");
        __syncthreads();
        const uint32_t sA = sb + (kt % NSTG) * STG;
        const uint32_t sB = sA + AST;
#pragma unroll
        for (int ks = 0; ks < 4; ++ks) {  // 4 x k16 per BK=64 stage
            uint32_t a[4][4], b[WNI][2];
#pragma unroll
            for (int mi = 0; mi < 4; ++mi) {
                uint32_t ad = sA + swz((wm + mi * 16 + ra) * 128 + (klo + 2 * ks) * 16);
                ldmx4(a[mi][0], a[mi][1], a[mi][2], a[mi][3], ad);
            }
#pragma unroll
            for (int p = 0; p < WNI / 2; ++p) {
                uint32_t ad = sB + swz((wn + p * 16 + brow) * 128 + (bk + 2 * ks) * 16);
                uint32_t r0, r1, r2, r3;
                ldmx4(r0, r1, r2, r3, ad);
                b[2 * p][0] = r0; b[2 * p][1] = r1;
                b[2 * p + 1][0] = r2; b[2 * p + 1][1] = r3;
            }
#pragma unroll
            for (int mi = 0; mi < 4; ++mi)
#pragma unroll
                for (int ni = 0; ni < WNI; ++ni)
                    mma_bf16(c[mi][ni], a[mi], b[ni]);
        }
        __syncthreads();
        if (kt + NSTG < kIters) load_stage<BNT, NSTG>(A, B, ldA, ldB, sb, kt + NSTG);
        cp_commit();  // constant group count
    }
}

// ---------------------------------------------------------------------------
// Fused pre-pass: W transpose, xs fp32->bf16, g_Xf zero, bv, out[0] = -sum(a).
constexpr int TW_BLK = (FD / 32) * (KD / 64);  // 8192
constexpr int CV_BLK = 2048;
constexpr int ZR_BLK = 2048;
constexpr int BV_BLK = 16;
constexpr int PRE_BLK = TW_BLK + CV_BLK + ZR_BLK + BV_BLK + 1;
__global__ void __launch_bounds__(256) k_pre(const float* __restrict__ xs,
                                             const float* __restrict__ W,
                                             const int* __restrict__ ys,
                                             const float* __restrict__ alphas,
                                             float* __restrict__ out) {
    const int bid = blockIdx.x;
    const int tid = threadIdx.x;
    if (bid < TW_BLK) {  // transpose 64(k) x 32(n) tile of W
        __shared__ float s[64][33];
        const int nb = (bid & 63) * 32, kb = (bid >> 6) * 64;
        const int tx = tid & 31, ty = tid >> 5;
#pragma unroll
        for (int r = 0; r < 64; r += 8)
            s[ty + r][tx] = W[(size_t)(kb + ty + r) * FD + nb + tx];
        __syncthreads();
#pragma unroll
        for (int rr = 0; rr < 4; rr++) {
            int n = ty + rr * 8;
            __nv_bfloat162 v = __floats2bfloat162_rn(s[2 * tx][n], s[2 * tx + 1][n]);
            *(__nv_bfloat162*)(g_Wt + (size_t)(nb + n) * KD + kb + 2 * tx) = v;
        }
    } else if (bid < TW_BLK + CV_BLK) {  // convert xs
        size_t i = (size_t)(bid - TW_BLK) * 256 + tid;
        const size_t n4 = (size_t)NP * KD / 4;
        const size_t stride = (size_t)CV_BLK * 256;
        __nv_bfloat162* o = (__nv_bfloat162*)g_xsb;
        const float4* in = (const float4*)xs;
        for (; i < n4; i += stride) {
            float4 v = in[i];
            o[2 * i] = __floats2bfloat162_rn(v.x, v.y);
            o[2 * i + 1] = __floats2bfloat162_rn(v.z, v.w);
        }
    } else if (bid < TW_BLK + CV_BLK + ZR_BLK) {  // zero g_Xf
        const int b = bid - TW_BLK - CV_BLK;
        float4* p = (float4*)g_Xf + (size_t)b * 1024 + tid;
#pragma unroll
        for (int t = 0; t < 4; t++) p[t * 256] = make_float4(0.f, 0.f, 0.f, 0.f);
    } else if (bid < TW_BLK + CV_BLK + ZR_BLK + BV_BLK) {  // bv
        const int i = (bid - TW_BLK - CV_BLK - ZR_BLK) * 256 + tid;
        g_bv[i] = alphas[i] * (float)(2 * ys[i] - 1);
    } else {  // out[0] = -sum(alphas)
        float s = 0.f;
        for (int t = tid; t < NP; t += 256) s += alphas[t];
#pragma unroll
        for (int o = 16; o > 0; o >>= 1) s += __shfl_xor_sync(0xffffffffu, s, o);
        __shared__ float red[8];
        if ((tid & 31) == 0) red[tid >> 5] = s;
        __syncthreads();
        if (tid == 0) {
            float t = 0.f;
            for (int q = 0; q < 8; q++) t += red[q];
            out[0] = -t;
        }
    }
}

// GEMM1 split-K: X += xs[kq] @ W[kq] -> g_Xf via fire-and-forget f32 atomics.
__global__ void __launch_bounds__(256, 1) k_gemm1() {
    float c[4][8][4];
#pragma unroll
    for (int i = 0; i < 4; i++)
#pragma unroll
        for (int j = 0; j < 8; j++)
#pragma unroll
            for (int k = 0; k < 4; k++) c[i][j][k] = 0.f;
    const int rowB = blockIdx.y * 128, colB = blockIdx.x * 256;
    const size_t koff = (size_t)blockIdx.z * KQ;
    gemm_mainloop<256, 8, 4>(g_xsb + (size_t)rowB * KD + koff,
                             g_Wt + (size_t)colB * KD + koff, KD, KD, KQ / BK, c);
    const int lane = threadIdx.x & 31, warp = threadIdx.x >> 5;
    const int wm = (warp >> 2) * 64, wn = (warp & 3) * 64;
#pragma unroll
    for (int mi = 0; mi < 4; mi++) {
        const int r0 = rowB + wm + mi * 16 + (lane >> 2);
#pragma unroll
        for (int ni = 0; ni < 8; ni++) {
            const int c0 = colB + wn + ni * 8 + (lane & 3) * 2;
            atomicAdd(&g_Xf[(size_t)r0 * FD + c0], c[mi][ni][0]);
            atomicAdd(&g_Xf[(size_t)r0 * FD + c0 + 1], c[mi][ni][1]);
            atomicAdd(&g_Xf[(size_t)(r0 + 8) * FD + c0], c[mi][ni][2]);
            atomicAdd(&g_Xf[(size_t)(r0 + 8) * FD + c0 + 1], c[mi][ni][3]);
        }
    }
}

// Combine: g_Xf fp32 -> g_Xb bf16 + row norms from ROUNDED values (exact
// diagonal cancellation in GEMM2). Warp per row.
__global__ void __launch_bounds__(256) k_combine() {
    const int row = blockIdx.x * 8 + (threadIdx.x >> 5);
    const int lane = threadIdx.x & 31;
    const float4* src = (const float4*)(g_Xf + (size_t)row * FD);
    uint2* dst = (uint2*)(g_Xb + (size_t)row * FD);
    float ss = 0.f;
#pragma unroll
    for (int it = 0; it < 16; it++) {
        float4 v = src[it * 32 + lane];
        __nv_bfloat162 b0 = __floats2bfloat162_rn(v.x, v.y);
        __nv_bfloat162 b1 = __floats2bfloat162_rn(v.z, v.w);
        uint2 u;
        u.x = *(uint32_t*)&b0;
        u.y = *(uint32_t*)&b1;
        dst[it * 32 + lane] = u;
        float2 f0 = __bfloat1622float2(b0), f1 = __bfloat1622float2(b1);
        ss += f0.x * f0.x + f0.y * f0.y + f1.x * f1.x + f1.y * f1.y;
    }
#pragma unroll
    for (int o = 16; o > 0; o >>= 1) ss += __shfl_xor_sync(0xffffffffu, ss, o);
    if (lane == 0) g_sq[row] = ss;
}

// GEMM2 fused, packed upper-triangle 1D grid: S = X_i @ X_j^T, then
// sum b_i b_j exp(-gamma*d2); off-diagonal tiles weighted x2; result
// atomically accumulated into out[0] (pre-initialized to -sum(alpha)).
__global__ void __launch_bounds__(256, 2) k_gemm2(float* __restrict__ out) {
    int ti = 0, rem = blockIdx.x;
    while (rem >= 32 - ti) { rem -= 32 - ti; ti++; }
    const int tj = ti + rem;
    float c[4][4][4];
#pragma unroll
    for (int i = 0; i < 4; i++)
#pragma unroll
        for (int j = 0; j < 4; j++)
#pragma unroll
            for (int k = 0; k < 4; k++) c[i][j][k] = 0.f;
    gemm_mainloop<128, 4, 3>(g_Xb + (size_t)ti * 128 * FD,
                             g_Xb + (size_t)tj * 128 * FD, FD, FD, FD / BK, c);
    const int lane = threadIdx.x & 31, warp = threadIdx.x >> 5;
    const int wm = (warp >> 2) * 64, wn = (warp & 3) * 32;
    float acc = 0.f;
#pragma unroll
    for (int mi = 0; mi < 4; mi++) {
        const int i0 = ti * 128 + wm + mi * 16 + (lane >> 2);
        const int i1 = i0 + 8;
        const float sqi0 = g_sq[i0], sqi1 = g_sq[i1];
        const float bi0 = g_bv[i0], bi1 = g_bv[i1];
#pragma unroll
        for (int ni = 0; ni < 4; ni++) {
            const int j0 = tj * 128 + wn + ni * 8 + (lane & 3) * 2;
            const int j1 = j0 + 1;
            const float sqj0 = g_sq[j0], sqj1 = g_sq[j1];
            const float bj0 = g_bv[j0], bj1 = g_bv[j1];
            acc += bi0 * bj0 * __expf(-GAMMA * fmaxf(sqi0 + sqj0 - 2.f * c[mi][ni][0], 0.f));
            acc += bi0 * bj1 * __expf(-GAMMA * fmaxf(sqi0 + sqj1 - 2.f * c[mi][ni][1], 0.f));
            acc += bi1 * bj0 * __expf(-GAMMA * fmaxf(sqi1 + sqj0 - 2.f * c[mi][ni][2], 0.f));
            acc += bi1 * bj1 * __expf(-GAMMA * fmaxf(sqi1 + sqj1 - 2.f * c[mi][ni][3], 0.f));
        }
    }
    if (ti != tj) acc *= 2.f;
#pragma unroll
    for (int o = 16; o > 0; o >>= 1) acc += __shfl_xor_sync(0xffffffffu, acc, o);
    extern __shared__ char smem[];
    float* red = (float*)smem;
    if (lane == 0) red[warp] = acc;
    __syncthreads();
    if (threadIdx.x == 0) {
        float s = 0.f;
        for (int q = 0; q < 8; q++) s += red[q];
        atomicAdd(out, 0.5f * s);
    }
}

// ---------------------------------------------------------------------------
constexpr int SMEM_G1 = 4 * (128 * 128 + 256 * 128);  // 192 KB
constexpr int SMEM_G2 = 3 * (128 * 128 + 128 * 128);  // 96 KB

extern "C" void kernel_launch(void* const* d_in, const int* in_sizes, int n_in,
                              void* d_out, int out_size) {
    (void)in_sizes; (void)n_in; (void)out_size;
    const float* xs = (const float*)d_in[0];
    const float* W = (const float*)d_in[1];
    const int* ys = (const int*)d_in[2];
    const float* alphas = (const float*)d_in[3];
    float* out = (float*)d_out;

    cudaFuncSetAttribute(k_gemm1, cudaFuncAttributeMaxDynamicSharedMemorySize,
                         SMEM_G1);
    cudaFuncSetAttribute(k_gemm2, cudaFuncAttributeMaxDynamicSharedMemorySize,
                         SMEM_G2);

    k_pre<<<PRE_BLK, 256>>>(xs, W, ys, alphas, out);
    k_gemm1<<<dim3(FD / 256, NP / 128, KSPLIT), 256, SMEM_G1>>>();
    k_combine<<<NP / 8, 256>>>();
    k_gemm2<<<(32 * 33) / 2, 256, SMEM_G2>>>(out);
}

// round 7
// speedup vs baseline: 1.8201x; 1.0175x over previous
#include <cuda_runtime.h>
#include <cuda_bf16.h>
#include <cstdint>

// Problem constants
constexpr int NP = 4096;   // data_length
constexpr int KD = 8192;   // T_IN * D_IN
constexpr int FD = 2048;   // F
constexpr float GAMMA = 1.0f / 2048.0f;

constexpr int BK = 64;
constexpr int KSPLIT = 4;             // GEMM1 split-K factor
constexpr int KQ = KD / KSPLIT;       // 2048 per split
constexpr size_t NPFD = (size_t)NP * FD;

// Scratch (device globals; no runtime allocation)
__device__ __nv_bfloat16 g_xsb[(size_t)NP * KD];  // xs bf16 (64 MB)
__device__ __nv_bfloat16 g_Wt[(size_t)FD * KD];   // W^T bf16 (32 MB)
__device__ float g_Xf[(size_t)KSPLIT * NPFD];     // split-K partials (128 MB)
__device__ __nv_bfloat16 g_Xb[NPFD];              // X bf16 (16 MB)
__device__ float g_sq[NP];
__device__ float g_bv[NP];

// ---------------------------------------------------------------------------
__device__ __forceinline__ uint32_t s2u(const void* p) {
    return (uint32_t)__cvta_generic_to_shared(p);
}
__device__ __forceinline__ uint32_t swz(uint32_t o) { return o ^ ((o >> 3) & 0x70); }
__device__ __forceinline__ void cpa16(uint32_t d, const void* g) {
    asm volatile("cp.async.cg.shared.global [%0], [%1], 16;\n" ::"r"(d), "l"(g));
}
__device__ __forceinline__ void cp_commit() {
    asm volatile("cp.async.commit_group;\n" ::: "memory");
}
__device__ __forceinline__ void ldmx4(uint32_t& r0, uint32_t& r1, uint32_t& r2,
                                      uint32_t& r3, uint32_t a) {
    asm volatile("ldmatrix.sync.aligned.m8n8.x4.shared.b16 {%0,%1,%2,%3}, [%4];\n"
                 : "=r"(r0), "=r"(r1), "=r"(r2), "=r"(r3) : "r"(a));
}
__device__ __forceinline__ void mma_bf16(float c[4], const uint32_t a[4],
                                         const uint32_t b[2]) {
    asm volatile(
        "mma.sync.aligned.m16n8k16.row.col.f32.bf16.bf16.f32 "
        "{%0,%1,%2,%3}, {%4,%5,%6,%7}, {%8,%9}, {%0,%1,%2,%3};\n"
        : "+f"(c[0]), "+f"(c[1]), "+f"(c[2]), "+f"(c[3])
        : "r"(a[0]), "r"(a[1]), "r"(a[2]), "r"(a[3]), "r"(b[0]), "r"(b[1]));
}

// Load one BK=64 stage: A[128 rows] + B[BNT rows], 128B swizzled rows.
template <int BNT, int NSTG>
__device__ __forceinline__ void load_stage(const __nv_bfloat16* A,
                                           const __nv_bfloat16* B, size_t ldA,
                                           size_t ldB, uint32_t sb, int kt) {
    constexpr int AST = 128 * 128;
    constexpr int STG = AST + BNT * 128;
    const int tid = threadIdx.x;
    const uint32_t sa = sb + (kt % NSTG) * STG;
    const uint32_t sbm = sa + AST;
    const __nv_bfloat16* As = A + (size_t)kt * BK;
    const __nv_bfloat16* Bs = B + (size_t)kt * BK;
#pragma unroll
    for (int t = 0; t < 4; t++) {
        int ch = tid + t * 256, r = ch >> 3, c = ch & 7;
        cpa16(sa + swz(r * 128 + c * 16), As + (size_t)r * ldA + c * 8);
    }
#pragma unroll
    for (int t = 0; t < BNT / 32; t++) {
        int ch = tid + t * 256, r = ch >> 3, c = ch & 7;
        cpa16(sbm + swz(r * 128 + c * 16), Bs + (size_t)r * ldB + c * 8);
    }
}

// NT GEMM mainloop: A [m][k], B [n][k] row-major bf16. 256 threads, 8 warps
// (2m x 4n), warp tile 64 x (WNI*8). Accum c[4][WNI][4].
template <int BNT, int WNI, int NSTG>
__device__ __forceinline__ void gemm_mainloop(const __nv_bfloat16* __restrict__ A,
                                              const __nv_bfloat16* __restrict__ B,
                                              size_t ldA, size_t ldB, int kIters,
                                              float c[4][WNI][4]) {
    constexpr int AST = 128 * 128;
    constexpr int STG = AST + BNT * 128;
    extern __shared__ char smem[];
    const uint32_t sb = s2u(smem);
    const int tid = threadIdx.x, lane = tid & 31, warp = tid >> 5;
    const int wm = (warp >> 2) * 64, wn = (warp & 3) * (WNI * 8);
    const int ra = lane & 15, klo = lane >> 4;
    const int bm8 = lane >> 3;
    const int brow = (lane & 7) + (bm8 >> 1) * 8;
    const int bk = bm8 & 1;

#pragma unroll
    for (int s = 0; s < NSTG; s++) {
        load_stage<BNT, NSTG>(A, B, ldA, ldB, sb, s);
        cp_commit();
    }

    for (int kt = 0; kt < kIters; ++kt) {
        asm volatile("cp.async.wait_group %0;\n" ::"n"(NSTG - 1) : "memory");
        __syncthreads();
        const uint32_t sA = sb + (kt % NSTG) * STG;
        const uint32_t sB = sA + AST;
#pragma unroll
        for (int ks = 0; ks < 4; ++ks) {  // 4 x k16 per BK=64 stage
            uint32_t a[4][4], b[WNI][2];
#pragma unroll
            for (int mi = 0; mi < 4; ++mi) {
                uint32_t ad = sA + swz((wm + mi * 16 + ra) * 128 + (klo + 2 * ks) * 16);
                ldmx4(a[mi][0], a[mi][1], a[mi][2], a[mi][3], ad);
            }
#pragma unroll
            for (int p = 0; p < WNI / 2; ++p) {
                uint32_t ad = sB + swz((wn + p * 16 + brow) * 128 + (bk + 2 * ks) * 16);
                uint32_t r0, r1, r2, r3;
                ldmx4(r0, r1, r2, r3, ad);
                b[2 * p][0] = r0; b[2 * p][1] = r1;
                b[2 * p + 1][0] = r2; b[2 * p + 1][1] = r3;
            }
#pragma unroll
            for (int mi = 0; mi < 4; ++mi)
#pragma unroll
                for (int ni = 0; ni < WNI; ++ni)
                    mma_bf16(c[mi][ni], a[mi], b[ni]);
        }
        __syncthreads();
        if (kt + NSTG < kIters) load_stage<BNT, NSTG>(A, B, ldA, ldB, sb, kt + NSTG);
        cp_commit();  // constant group count
    }
}

// ---------------------------------------------------------------------------
// Fused pre-pass: W transpose, xs fp32->bf16, bv, out[0] = -sum(alphas).
constexpr int TW_BLK = (FD / 32) * (KD / 64);  // 8192
constexpr int CV_BLK = 2048;
constexpr int BV_BLK = 16;
constexpr int PRE_BLK = TW_BLK + CV_BLK + BV_BLK + 1;
__global__ void __launch_bounds__(256) k_pre(const float* __restrict__ xs,
                                             const float* __restrict__ W,
                                             const int* __restrict__ ys,
                                             const float* __restrict__ alphas,
                                             float* __restrict__ out) {
    const int bid = blockIdx.x;
    const int tid = threadIdx.x;
    if (bid < TW_BLK) {  // transpose 64(k) x 32(n) tile of W
        __shared__ float s[64][33];
        const int nb = (bid & 63) * 32, kb = (bid >> 6) * 64;
        const int tx = tid & 31, ty = tid >> 5;
#pragma unroll
        for (int r = 0; r < 64; r += 8)
            s[ty + r][tx] = W[(size_t)(kb + ty + r) * FD + nb + tx];
        __syncthreads();
#pragma unroll
        for (int rr = 0; rr < 4; rr++) {
            int n = ty + rr * 8;
            __nv_bfloat162 v = __floats2bfloat162_rn(s[2 * tx][n], s[2 * tx + 1][n]);
            *(__nv_bfloat162*)(g_Wt + (size_t)(nb + n) * KD + kb + 2 * tx) = v;
        }
    } else if (bid < TW_BLK + CV_BLK) {  // convert xs
        size_t i = (size_t)(bid - TW_BLK) * 256 + tid;
        const size_t n4 = (size_t)NP * KD / 4;
        const size_t stride = (size_t)CV_BLK * 256;
        __nv_bfloat162* o = (__nv_bfloat162*)g_xsb;
        const float4* in = (const float4*)xs;
        for (; i < n4; i += stride) {
            float4 v = in[i];
            o[2 * i] = __floats2bfloat162_rn(v.x, v.y);
            o[2 * i + 1] = __floats2bfloat162_rn(v.z, v.w);
        }
    } else if (bid < TW_BLK + CV_BLK + BV_BLK) {  // bv
        const int i = (bid - TW_BLK - CV_BLK) * 256 + tid;
        g_bv[i] = alphas[i] * (float)(2 * ys[i] - 1);
    } else {  // out[0] = -sum(alphas)
        float s = 0.f;
        for (int t = tid; t < NP; t += 256) s += alphas[t];
#pragma unroll
        for (int o = 16; o > 0; o >>= 1) s += __shfl_xor_sync(0xffffffffu, s, o);
        __shared__ float red[8];
        if ((tid & 31) == 0) red[tid >> 5] = s;
        __syncthreads();
        if (tid == 0) {
            float t = 0.f;
            for (int q = 0; q < 8; q++) t += red[q];
            out[0] = -t;
        }
    }
}

// GEMM1 split-K: slab z = xs[:, zKQ:(z+1)KQ] @ W[zKQ:(z+1)KQ, :], plain stores.
__global__ void __launch_bounds__(256, 1) k_gemm1() {
    float c[4][8][4];
#pragma unroll
    for (int i = 0; i < 4; i++)
#pragma unroll
        for (int j = 0; j < 8; j++)
#pragma unroll
            for (int k = 0; k < 4; k++) c[i][j][k] = 0.f;
    const int rowB = blockIdx.y * 128, colB = blockIdx.x * 256;
    const size_t koff = (size_t)blockIdx.z * KQ;
    gemm_mainloop<256, 8, 4>(g_xsb + (size_t)rowB * KD + koff,
                             g_Wt + (size_t)colB * KD + koff, KD, KD, KQ / BK, c);
    float* slab = g_Xf + (size_t)blockIdx.z * NPFD;
    const int lane = threadIdx.x & 31, warp = threadIdx.x >> 5;
    const int wm = (warp >> 2) * 64, wn = (warp & 3) * 64;
#pragma unroll
    for (int mi = 0; mi < 4; mi++) {
        const int r0 = rowB + wm + mi * 16 + (lane >> 2);
#pragma unroll
        for (int ni = 0; ni < 8; ni++) {
            const int c0 = colB + wn + ni * 8 + (lane & 3) * 2;
            *(float2*)(slab + (size_t)r0 * FD + c0) =
                make_float2(c[mi][ni][0], c[mi][ni][1]);
            *(float2*)(slab + (size_t)(r0 + 8) * FD + c0) =
                make_float2(c[mi][ni][2], c[mi][ni][3]);
        }
    }
}

// Combine: sum 4 slabs -> bf16 g_Xb + row norms from ROUNDED values (exact
// diagonal cancellation in GEMM2). Warp per row.
__global__ void __launch_bounds__(256) k_combine() {
    const int row = blockIdx.x * 8 + (threadIdx.x >> 5);
    const int lane = threadIdx.x & 31;
    const float4* s0 = (const float4*)(g_Xf + (size_t)row * FD);
    const float4* s1 = (const float4*)(g_Xf + NPFD + (size_t)row * FD);
    const float4* s2 = (const float4*)(g_Xf + 2 * NPFD + (size_t)row * FD);
    const float4* s3 = (const float4*)(g_Xf + 3 * NPFD + (size_t)row * FD);
    uint2* dst = (uint2*)(g_Xb + (size_t)row * FD);
    float ss = 0.f;
#pragma unroll
    for (int it = 0; it < 16; it++) {
        const int idx = it * 32 + lane;
        float4 a = s0[idx], b = s1[idx], cc = s2[idx], d = s3[idx];
        float vx = (a.x + b.x) + (cc.x + d.x);
        float vy = (a.y + b.y) + (cc.y + d.y);
        float vz = (a.z + b.z) + (cc.z + d.z);
        float vw = (a.w + b.w) + (cc.w + d.w);
        __nv_bfloat162 b0 = __floats2bfloat162_rn(vx, vy);
        __nv_bfloat162 b1 = __floats2bfloat162_rn(vz, vw);
        uint2 u;
        u.x = *(uint32_t*)&b0;
        u.y = *(uint32_t*)&b1;
        dst[idx] = u;
        float2 f0 = __bfloat1622float2(b0), f1 = __bfloat1622float2(b1);
        ss += f0.x * f0.x + f0.y * f0.y + f1.x * f1.x + f1.y * f1.y;
    }
#pragma unroll
    for (int o = 16; o > 0; o >>= 1) ss += __shfl_xor_sync(0xffffffffu, ss, o);
    if (lane == 0) g_sq[row] = ss;
}

// GEMM2 fused, packed upper-triangle 1D grid: S = X_i @ X_j^T, then
// sum b_i b_j exp(-gamma*d2); off-diagonal tiles weighted x2; result
// atomically accumulated into out[0] (pre-initialized to -sum(alpha)).
__global__ void __launch_bounds__(256, 2) k_gemm2(float* __restrict__ out) {
    int ti = 0, rem = blockIdx.x;
    while (rem >= 32 - ti) { rem -= 32 - ti; ti++; }
    const int tj = ti + rem;
    float c[4][4][4];
#pragma unroll
    for (int i = 0; i < 4; i++)
#pragma unroll
        for (int j = 0; j < 4; j++)
#pragma unroll
            for (int k = 0; k < 4; k++) c[i][j][k] = 0.f;
    gemm_mainloop<128, 4, 3>(g_Xb + (size_t)ti * 128 * FD,
                             g_Xb + (size_t)tj * 128 * FD, FD, FD, FD / BK, c);
    const int lane = threadIdx.x & 31, warp = threadIdx.x >> 5;
    const int wm = (warp >> 2) * 64, wn = (warp & 3) * 32;
    float acc = 0.f;
#pragma unroll
    for (int mi = 0; mi < 4; mi++) {
        const int i0 = ti * 128 + wm + mi * 16 + (lane >> 2);
        const int i1 = i0 + 8;
        const float sqi0 = g_sq[i0], sqi1 = g_sq[i1];
        const float bi0 = g_bv[i0], bi1 = g_bv[i1];
#pragma unroll
        for (int ni = 0; ni < 4; ni++) {
            const int j0 = tj * 128 + wn + ni * 8 + (lane & 3) * 2;
            const int j1 = j0 + 1;
            const float sqj0 = g_sq[j0], sqj1 = g_sq[j1];
            const float bj0 = g_bv[j0], bj1 = g_bv[j1];
            acc += bi0 * bj0 * __expf(-GAMMA * fmaxf(sqi0 + sqj0 - 2.f * c[mi][ni][0], 0.f));
            acc += bi0 * bj1 * __expf(-GAMMA * fmaxf(sqi0 + sqj1 - 2.f * c[mi][ni][1], 0.f));
            acc += bi1 * bj0 * __expf(-GAMMA * fmaxf(sqi1 + sqj0 - 2.f * c[mi][ni][2], 0.f));
            acc += bi1 * bj1 * __expf(-GAMMA * fmaxf(sqi1 + sqj1 - 2.f * c[mi][ni][3], 0.f));
        }
    }
    if (ti != tj) acc *= 2.f;
#pragma unroll
    for (int o = 16; o > 0; o >>= 1) acc += __shfl_xor_sync(0xffffffffu, acc, o);
    extern __shared__ char smem[];
    float* red = (float*)smem;
    if (lane == 0) red[warp] = acc;
    __syncthreads();
    if (threadIdx.x == 0) {
        float s = 0.f;
        for (int q = 0; q < 8; q++) s += red[q];
        atomicAdd(out, 0.5f * s);
    }
}

// ---------------------------------------------------------------------------
constexpr int SMEM_G1 = 4 * (128 * 128 + 256 * 128);  // 192 KB
constexpr int SMEM_G2 = 3 * (128 * 128 + 128 * 128);  // 96 KB

extern "C" void kernel_launch(void* const* d_in, const int* in_sizes, int n_in,
                              void* d_out, int out_size) {
    (void)in_sizes; (void)n_in; (void)out_size;
    const float* xs = (const float*)d_in[0];
    const float* W = (const float*)d_in[1];
    const int* ys = (const int*)d_in[2];
    const float* alphas = (const float*)d_in[3];
    float* out = (float*)d_out;

    cudaFuncSetAttribute(k_gemm1, cudaFuncAttributeMaxDynamicSharedMemorySize,
                         SMEM_G1);
    cudaFuncSetAttribute(k_gemm2, cudaFuncAttributeMaxDynamicSharedMemorySize,
                         SMEM_G2);

    k_pre<<<PRE_BLK, 256>>>(xs, W, ys, alphas, out);
    k_gemm1<<<dim3(FD / 256, NP / 128, KSPLIT), 256, SMEM_G1>>>();
    k_combine<<<NP / 8, 256>>>();
    k_gemm2<<<(32 * 33) / 2, 256, SMEM_G2>>>(out);
}

// round 10
// speedup vs baseline: 1.8259x; 1.0032x over previous
#include <cuda_runtime.h>
#include <cuda_bf16.h>
#include <cstdint>

// Problem constants
constexpr int NP = 4096;   // data_length
constexpr int KD = 8192;   // T_IN * D_IN
constexpr int FD = 2048;   // F
constexpr float GAMMA = 1.0f / 2048.0f;

constexpr int BK = 64;
constexpr int KSPLIT = 4;             // GEMM1 split-K factor
constexpr int KQ = KD / KSPLIT;       // 2048 per split
constexpr size_t NPFD = (size_t)NP * FD;

// Scratch (device globals; no runtime allocation)
__device__ __nv_bfloat16 g_xsb[(size_t)NP * KD];  // xs bf16 (64 MB)
__device__ __nv_bfloat16 g_Wt[(size_t)FD * KD];   // W^T bf16 (32 MB)
__device__ float g_Xf[(size_t)KSPLIT * NPFD];     // split-K partials (128 MB)
__device__ __nv_bfloat16 g_Xb[NPFD];              // X bf16 (16 MB)
__device__ float g_sq[NP];
__device__ float g_bv[NP];

// ---------------------------------------------------------------------------
__device__ __forceinline__ uint32_t s2u(const void* p) {
    return (uint32_t)__cvta_generic_to_shared(p);
}
__device__ __forceinline__ uint32_t swz(uint32_t o) { return o ^ ((o >> 3) & 0x70); }
__device__ __forceinline__ void cpa16(uint32_t d, const void* g) {
    asm volatile("cp.async.cg.shared.global [%0], [%1], 16;\n" ::"r"(d), "l"(g));
}
__device__ __forceinline__ void cp_commit() {
    asm volatile("cp.async.commit_group;\n" ::: "memory");
}
__device__ __forceinline__ void ldmx4(uint32_t& r0, uint32_t& r1, uint32_t& r2,
                                      uint32_t& r3, uint32_t a) {
    asm volatile("ldmatrix.sync.aligned.m8n8.x4.shared.b16 {%0,%1,%2,%3}, [%4];\n"
                 : "=r"(r0), "=r"(r1), "=r"(r2), "=r"(r3) : "r"(a));
}
__device__ __forceinline__ void mma_bf16(float c[4], const uint32_t a[4],
                                         const uint32_t b[2]) {
    asm volatile(
        "mma.sync.aligned.m16n8k16.row.col.f32.bf16.bf16.f32 "
        "{%0,%1,%2,%3}, {%4,%5,%6,%7}, {%8,%9}, {%0,%1,%2,%3};\n"
        : "+f"(c[0]), "+f"(c[1]), "+f"(c[2]), "+f"(c[3])
        : "r"(a[0]), "r"(a[1]), "r"(a[2]), "r"(a[3]), "r"(b[0]), "r"(b[1]));
}

// Load one BK=64 stage: A[128 rows] + B[BNT rows], 128B swizzled rows.
template <int BNT, int NSTG>
__device__ __forceinline__ void load_stage(const __nv_bfloat16* A,
                                           const __nv_bfloat16* B, size_t ldA,
                                           size_t ldB, uint32_t sb, int kt) {
    constexpr int AST = 128 * 128;
    constexpr int STG = AST + BNT * 128;
    const int tid = threadIdx.x;
    const uint32_t sa = sb + (kt % NSTG) * STG;
    const uint32_t sbm = sa + AST;
    const __nv_bfloat16* As = A + (size_t)kt * BK;
    const __nv_bfloat16* Bs = B + (size_t)kt * BK;
#pragma unroll
    for (int t = 0; t < 4; t++) {
        int ch = tid + t * 256, r = ch >> 3, c = ch & 7;
        cpa16(sa + swz(r * 128 + c * 16), As + (size_t)r * ldA + c * 8);
    }
#pragma unroll
    for (int t = 0; t < BNT / 32; t++) {
        int ch = tid + t * 256, r = ch >> 3, c = ch & 7;
        cpa16(sbm + swz(r * 128 + c * 16), Bs + (size_t)r * ldB + c * 8);
    }
}

// NT GEMM mainloop, single-barrier multistage pipeline.
// A [m][k], B [n][k] row-major bf16. 256 threads, 8 warps (2m x 4n),
// warp tile 64 x (WNI*8). Accum c[4][WNI][4]. DB = frag double-buffering.
template <int BNT, int WNI, int NSTG, bool DB>
__device__ __forceinline__ void gemm_mainloop(const __nv_bfloat16* __restrict__ A,
                                              const __nv_bfloat16* __restrict__ B,
                                              size_t ldA, size_t ldB, int kIters,
                                              float c[4][WNI][4]) {
    constexpr int AST = 128 * 128;
    constexpr int STG = AST + BNT * 128;
    extern __shared__ char smem[];
    const uint32_t sb = s2u(smem);
    const int tid = threadIdx.x, lane = tid & 31, warp = tid >> 5;
    const int wm = (warp >> 2) * 64, wn = (warp & 3) * (WNI * 8);
    const int ra = lane & 15, klo = lane >> 4;
    const int bm8 = lane >> 3;
    const int brow = (lane & 7) + (bm8 >> 1) * 8;
    const int bk = bm8 & 1;

    auto lda_frags = [&](uint32_t sA, uint32_t sB, int ks, uint32_t a[4][4],
                         uint32_t b[WNI][2]) {
#pragma unroll
        for (int mi = 0; mi < 4; ++mi) {
            uint32_t ad = sA + swz((wm + mi * 16 + ra) * 128 + (klo + 2 * ks) * 16);
            ldmx4(a[mi][0], a[mi][1], a[mi][2], a[mi][3], ad);
        }
#pragma unroll
        for (int p = 0; p < WNI / 2; ++p) {
            uint32_t ad = sB + swz((wn + p * 16 + brow) * 128 + (bk + 2 * ks) * 16);
            uint32_t r0, r1, r2, r3;
            ldmx4(r0, r1, r2, r3, ad);
            b[2 * p][0] = r0; b[2 * p][1] = r1;
            b[2 * p + 1][0] = r2; b[2 * p + 1][1] = r3;
        }
    };

    // Prologue: fill NSTG-1 stages (the last buffer is filled inside iter 0).
#pragma unroll
    for (int s = 0; s < NSTG - 1; s++) {
        load_stage<BNT, NSTG>(A, B, ldA, ldB, sb, s);
        cp_commit();
    }

    for (int kt = 0; kt < kIters; ++kt) {
        asm volatile("cp.async.wait_group %0;\n" ::"n"(NSTG - 2) : "memory");
        __syncthreads();
        // Load stage kt+NSTG-1 into buffer (kt-1)%NSTG: consumed in iter kt-1,
        // all warps are past it (barrier above). Overlaps this iter's MMAs.
        if (kt + NSTG - 1 < kIters)
            load_stage<BNT, NSTG>(A, B, ldA, ldB, sb, kt + NSTG - 1);
        cp_commit();  // constant group count

        const uint32_t sA = sb + (kt % NSTG) * STG;
        const uint32_t sB = sA + AST;
        if (DB) {
            uint32_t a[2][4][4], b[2][WNI][2];
            lda_frags(sA, sB, 0, a[0], b[0]);
#pragma unroll
            for (int ks = 0; ks < 4; ++ks) {
                const int cur = ks & 1;
                if (ks < 3) lda_frags(sA, sB, ks + 1, a[cur ^ 1], b[cur ^ 1]);
#pragma unroll
                for (int mi = 0; mi < 4; ++mi)
#pragma unroll
                    for (int ni = 0; ni < WNI; ++ni)
                        mma_bf16(c[mi][ni], a[cur][mi], b[cur][ni]);
            }
        } else {
#pragma unroll
            for (int ks = 0; ks < 4; ++ks) {
                uint32_t a[4][4], b[WNI][2];
                lda_frags(sA, sB, ks, a, b);
#pragma unroll
                for (int mi = 0; mi < 4; ++mi)
#pragma unroll
                    for (int ni = 0; ni < WNI; ++ni)
                        mma_bf16(c[mi][ni], a[mi], b[ni]);
            }
        }
    }
    __syncthreads();  // protect smem reuse by caller epilogues
}

// ---------------------------------------------------------------------------
// Fused pre-pass: W transpose, xs fp32->bf16, bv, out[0] = -sum(alphas).
constexpr int TW_BLK = (FD / 32) * (KD / 64);  // 8192
constexpr int CV_BLK = 2048;
constexpr int BV_BLK = 16;
constexpr int PRE_BLK = TW_BLK + CV_BLK + BV_BLK + 1;
__global__ void __launch_bounds__(256) k_pre(const float* __restrict__ xs,
                                             const float* __restrict__ W,
                                             const int* __restrict__ ys,
                                             const float* __restrict__ alphas,
                                             float* __restrict__ out) {
    const int bid = blockIdx.x;
    const int tid = threadIdx.x;
    if (bid < TW_BLK) {  // transpose 64(k) x 32(n) tile of W
        __shared__ float s[64][33];
        const int nb = (bid & 63) * 32, kb = (bid >> 6) * 64;
        const int tx = tid & 31, ty = tid >> 5;
#pragma unroll
        for (int r = 0; r < 64; r += 8)
            s[ty + r][tx] = W[(size_t)(kb + ty + r) * FD + nb + tx];
        __syncthreads();
#pragma unroll
        for (int rr = 0; rr < 4; rr++) {
            int n = ty + rr * 8;
            __nv_bfloat162 v = __floats2bfloat162_rn(s[2 * tx][n], s[2 * tx + 1][n]);
            *(__nv_bfloat162*)(g_Wt + (size_t)(nb + n) * KD + kb + 2 * tx) = v;
        }
    } else if (bid < TW_BLK + CV_BLK) {  // convert xs
        size_t i = (size_t)(bid - TW_BLK) * 256 + tid;
        const size_t n4 = (size_t)NP * KD / 4;
        const size_t stride = (size_t)CV_BLK * 256;
        __nv_bfloat162* o = (__nv_bfloat162*)g_xsb;
        const float4* in = (const float4*)xs;
        for (; i < n4; i += stride) {
            float4 v = in[i];
            o[2 * i] = __floats2bfloat162_rn(v.x, v.y);
            o[2 * i + 1] = __floats2bfloat162_rn(v.z, v.w);
        }
    } else if (bid < TW_BLK + CV_BLK + BV_BLK) {  // bv
        const int i = (bid - TW_BLK - CV_BLK) * 256 + tid;
        g_bv[i] = alphas[i] * (float)(2 * ys[i] - 1);
    } else {  // out[0] = -sum(alphas)
        float s = 0.f;
        for (int t = tid; t < NP; t += 256) s += alphas[t];
#pragma unroll
        for (int o = 16; o > 0; o >>= 1) s += __shfl_xor_sync(0xffffffffu, s, o);
        __shared__ float red[8];
        if ((tid & 31) == 0) red[tid >> 5] = s;
        __syncthreads();
        if (tid == 0) {
            float t = 0.f;
            for (int q = 0; q < 8; q++) t += red[q];
            out[0] = -t;
        }
    }
}

// GEMM1 split-K: slab z = xs[:, zKQ:(z+1)KQ] @ W[zKQ:(z+1)KQ, :], plain stores.
__global__ void __launch_bounds__(256, 1) k_gemm1() {
    float c[4][8][4];
#pragma unroll
    for (int i = 0; i < 4; i++)
#pragma unroll
        for (int j = 0; j < 8; j++)
#pragma unroll
            for (int k = 0; k < 4; k++) c[i][j][k] = 0.f;
    const int rowB = blockIdx.y * 128, colB = blockIdx.x * 256;
    const size_t koff = (size_t)blockIdx.z * KQ;
    gemm_mainloop<256, 8, 4, true>(g_xsb + (size_t)rowB * KD + koff,
                                   g_Wt + (size_t)colB * KD + koff, KD, KD,
                                   KQ / BK, c);
    float* slab = g_Xf + (size_t)blockIdx.z * NPFD;
    const int lane = threadIdx.x & 31, warp = threadIdx.x >> 5;
    const int wm = (warp >> 2) * 64, wn = (warp & 3) * 64;
#pragma unroll
    for (int mi = 0; mi < 4; mi++) {
        const int r0 = rowB + wm + mi * 16 + (lane >> 2);
#pragma unroll
        for (int ni = 0; ni < 8; ni++) {
            const int c0 = colB + wn + ni * 8 + (lane & 3) * 2;
            *(float2*)(slab + (size_t)r0 * FD + c0) =
                make_float2(c[mi][ni][0], c[mi][ni][1]);
            *(float2*)(slab + (size_t)(r0 + 8) * FD + c0) =
                make_float2(c[mi][ni][2], c[mi][ni][3]);
        }
    }
}

// Combine: sum 4 slabs -> bf16 g_Xb + row norms from ROUNDED values (exact
// diagonal cancellation in GEMM2). Warp per row.
__global__ void __launch_bounds__(256) k_combine() {
    const int row = blockIdx.x * 8 + (threadIdx.x >> 5);
    const int lane = threadIdx.x & 31;
    const float4* s0 = (const float4*)(g_Xf + (size_t)row * FD);
    const float4* s1 = (const float4*)(g_Xf + NPFD + (size_t)row * FD);
    const float4* s2 = (const float4*)(g_Xf + 2 * NPFD + (size_t)row * FD);
    const float4* s3 = (const float4*)(g_Xf + 3 * NPFD + (size_t)row * FD);
    uint2* dst = (uint2*)(g_Xb + (size_t)row * FD);
    float ss = 0.f;
#pragma unroll
    for (int it = 0; it < 16; it++) {
        const int idx = it * 32 + lane;
        float4 a = s0[idx], b = s1[idx], cc = s2[idx], d = s3[idx];
        float vx = (a.x + b.x) + (cc.x + d.x);
        float vy = (a.y + b.y) + (cc.y + d.y);
        float vz = (a.z + b.z) + (cc.z + d.z);
        float vw = (a.w + b.w) + (cc.w + d.w);
        __nv_bfloat162 b0 = __floats2bfloat162_rn(vx, vy);
        __nv_bfloat162 b1 = __floats2bfloat162_rn(vz, vw);
        uint2 u;
        u.x = *(uint32_t*)&b0;
        u.y = *(uint32_t*)&b1;
        dst[idx] = u;
        float2 f0 = __bfloat1622float2(b0), f1 = __bfloat1622float2(b1);
        ss += f0.x * f0.x + f0.y * f0.y + f1.x * f1.x + f1.y * f1.y;
    }
#pragma unroll
    for (int o = 16; o > 0; o >>= 1) ss += __shfl_xor_sync(0xffffffffu, ss, o);
    if (lane == 0) g_sq[row] = ss;
}

// GEMM2 fused, packed upper-triangle 1D grid: S = X_i @ X_j^T, then
// sum b_i b_j exp(-gamma*d2); off-diagonal tiles weighted x2; result
// atomically accumulated into out[0] (pre-initialized to -sum(alpha)).
__global__ void __launch_bounds__(256, 2) k_gemm2(float* __restrict__ out) {
    int ti = 0, rem = blockIdx.x;
    while (rem >= 32 - ti) { rem -= 32 - ti; ti++; }
    const int tj = ti + rem;
    float c[4][4][4];
#pragma unroll
    for (int i = 0; i < 4; i++)
#pragma unroll
        for (int j = 0; j < 4; j++)
#pragma unroll
            for (int k = 0; k < 4; k++) c[i][j][k] = 0.f;
    gemm_mainloop<128, 4, 3, false>(g_Xb + (size_t)ti * 128 * FD,
                                    g_Xb + (size_t)tj * 128 * FD, FD, FD,
                                    FD / BK, c);
    const int lane = threadIdx.x & 31, warp = threadIdx.x >> 5;
    const int wm = (warp >> 2) * 64, wn = (warp & 3) * 32;
    float acc = 0.f;
#pragma unroll
    for (int mi = 0; mi < 4; mi++) {
        const int i0 = ti * 128 + wm + mi * 16 + (lane >> 2);
        const int i1 = i0 + 8;
        const float sqi0 = g_sq[i0], sqi1 = g_sq[i1];
        const float bi0 = g_bv[i0], bi1 = g_bv[i1];
#pragma unroll
        for (int ni = 0; ni < 4; ni++) {
            const int j0 = tj * 128 + wn + ni * 8 + (lane & 3) * 2;
            const int j1 = j0 + 1;
            const float sqj0 = g_sq[j0], sqj1 = g_sq[j1];
            const float bj0 = g_bv[j0], bj1 = g_bv[j1];
            acc += bi0 * bj0 * __expf(-GAMMA * fmaxf(sqi0 + sqj0 - 2.f * c[mi][ni][0], 0.f));
            acc += bi0 * bj1 * __expf(-GAMMA * fmaxf(sqi0 + sqj1 - 2.f * c[mi][ni][1], 0.f));
            acc += bi1 * bj0 * __expf(-GAMMA * fmaxf(sqi1 + sqj0 - 2.f * c[mi][ni][2], 0.f));
            acc += bi1 * bj1 * __expf(-GAMMA * fmaxf(sqi1 + sqj1 - 2.f * c[mi][ni][3], 0.f));
        }
    }
    if (ti != tj) acc *= 2.f;
#pragma unroll
    for (int o = 16; o > 0; o >>= 1) acc += __shfl_xor_sync(0xffffffffu, acc, o);
    extern __shared__ char smem[];
    float* red = (float*)smem;
    if (lane == 0) red[warp] = acc;
    __syncthreads();
    if (threadIdx.x == 0) {
        float s = 0.f;
        for (int q = 0; q < 8; q++) s += red[q];
        atomicAdd(out, 0.5f * s);
    }
}

// ---------------------------------------------------------------------------
constexpr int SMEM_G1 = 4 * (128 * 128 + 256 * 128);  // 192 KB
constexpr int SMEM_G2 = 3 * (128 * 128 + 128 * 128);  // 96 KB

extern "C" void kernel_launch(void* const* d_in, const int* in_sizes, int n_in,
                              void* d_out, int out_size) {
    (void)in_sizes; (void)n_in; (void)out_size;
    const float* xs = (const float*)d_in[0];
    const float* W = (const float*)d_in[1];
    const int* ys = (const int*)d_in[2];
    const float* alphas = (const float*)d_in[3];
    float* out = (float*)d_out;

    cudaFuncSetAttribute(k_gemm1, cudaFuncAttributeMaxDynamicSharedMemorySize,
                         SMEM_G1);
    cudaFuncSetAttribute(k_gemm2, cudaFuncAttributeMaxDynamicSharedMemorySize,
                         SMEM_G2);

    k_pre<<<PRE_BLK, 256>>>(xs, W, ys, alphas, out);
    k_gemm1<<<dim3(FD / 256, NP / 128, KSPLIT), 256, SMEM_G1>>>();
    k_combine<<<NP / 8, 256>>>();
    k_gemm2<<<(32 * 33) / 2, 256, SMEM_G2>>>(out);
}

// round 11
// speedup vs baseline: 1.8579x; 1.0176x over previous
#include <cuda_runtime.h>
#include <cuda_bf16.h>
#include <cstdint>

// Problem constants
constexpr int NP = 4096;   // data_length
constexpr int KD = 8192;   // T_IN * D_IN
constexpr int FD = 2048;   // F
constexpr float GAMMA = 1.0f / 2048.0f;

constexpr int BK = 64;
constexpr int KSPLIT = 4;             // GEMM1 split-K factor
constexpr int KQ = KD / KSPLIT;       // 2048 per split
constexpr size_t NPFD = (size_t)NP * FD;

// Scratch (device globals; no runtime allocation)
__device__ __nv_bfloat16 g_xsb[(size_t)NP * KD];      // xs bf16 (64 MB)
__device__ __nv_bfloat16 g_Wt[(size_t)FD * KD];       // W^T bf16 (32 MB)
__device__ __nv_bfloat16 g_Xh[(size_t)KSPLIT * NPFD]; // split-K slabs bf16 (64 MB)
__device__ __nv_bfloat16 g_Xb[NPFD];                  // X bf16 (16 MB)
__device__ float g_sq[NP];
__device__ float g_bv[NP];

// ---------------------------------------------------------------------------
__device__ __forceinline__ uint32_t s2u(const void* p) {
    return (uint32_t)__cvta_generic_to_shared(p);
}
__device__ __forceinline__ uint32_t swz(uint32_t o) { return o ^ ((o >> 3) & 0x70); }
__device__ __forceinline__ void cpa16(uint32_t d, const void* g) {
    asm volatile("cp.async.cg.shared.global [%0], [%1], 16;\n" ::"r"(d), "l"(g));
}
__device__ __forceinline__ void cp_commit() {
    asm volatile("cp.async.commit_group;\n" ::: "memory");
}
__device__ __forceinline__ void ldmx4(uint32_t& r0, uint32_t& r1, uint32_t& r2,
                                      uint32_t& r3, uint32_t a) {
    asm volatile("ldmatrix.sync.aligned.m8n8.x4.shared.b16 {%0,%1,%2,%3}, [%4];\n"
                 : "=r"(r0), "=r"(r1), "=r"(r2), "=r"(r3) : "r"(a));
}
__device__ __forceinline__ void mma_bf16(float c[4], const uint32_t a[4],
                                         const uint32_t b[2]) {
    asm volatile(
        "mma.sync.aligned.m16n8k16.row.col.f32.bf16.bf16.f32 "
        "{%0,%1,%2,%3}, {%4,%5,%6,%7}, {%8,%9}, {%0,%1,%2,%3};\n"
        : "+f"(c[0]), "+f"(c[1]), "+f"(c[2]), "+f"(c[3])
        : "r"(a[0]), "r"(a[1]), "r"(a[2]), "r"(a[3]), "r"(b[0]), "r"(b[1]));
}

// Load one BK=64 stage: A[128 rows] + B[BNT rows], 128B swizzled rows.
template <int BNT, int NSTG>
__device__ __forceinline__ void load_stage(const __nv_bfloat16* A,
                                           const __nv_bfloat16* B, size_t ldA,
                                           size_t ldB, uint32_t sb, int kt) {
    constexpr int AST = 128 * 128;
    constexpr int STG = AST + BNT * 128;
    const int tid = threadIdx.x;
    const uint32_t sa = sb + (kt % NSTG) * STG;
    const uint32_t sbm = sa + AST;
    const __nv_bfloat16* As = A + (size_t)kt * BK;
    const __nv_bfloat16* Bs = B + (size_t)kt * BK;
#pragma unroll
    for (int t = 0; t < 4; t++) {
        int ch = tid + t * 256, r = ch >> 3, c = ch & 7;
        cpa16(sa + swz(r * 128 + c * 16), As + (size_t)r * ldA + c * 8);
    }
#pragma unroll
    for (int t = 0; t < BNT / 32; t++) {
        int ch = tid + t * 256, r = ch >> 3, c = ch & 7;
        cpa16(sbm + swz(r * 128 + c * 16), Bs + (size_t)r * ldB + c * 8);
    }
}

// NT GEMM mainloop, single-barrier multistage pipeline.
// A [m][k], B [n][k] row-major bf16. 256 threads, 8 warps (2m x 4n),
// warp tile 64 x (WNI*8). Accum c[4][WNI][4]. Frag double-buffered.
template <int BNT, int WNI, int NSTG>
__device__ __forceinline__ void gemm_mainloop(const __nv_bfloat16* __restrict__ A,
                                              const __nv_bfloat16* __restrict__ B,
                                              size_t ldA, size_t ldB, int kIters,
                                              float c[4][WNI][4]) {
    constexpr int AST = 128 * 128;
    constexpr int STG = AST + BNT * 128;
    extern __shared__ char smem[];
    const uint32_t sb = s2u(smem);
    const int tid = threadIdx.x, lane = tid & 31, warp = tid >> 5;
    const int wm = (warp >> 2) * 64, wn = (warp & 3) * (WNI * 8);
    const int ra = lane & 15, klo = lane >> 4;
    const int bm8 = lane >> 3;
    const int brow = (lane & 7) + (bm8 >> 1) * 8;
    const int bk = bm8 & 1;

    auto lda_frags = [&](uint32_t sA, uint32_t sB, int ks, uint32_t a[4][4],
                         uint32_t b[WNI][2]) {
#pragma unroll
        for (int mi = 0; mi < 4; ++mi) {
            uint32_t ad = sA + swz((wm + mi * 16 + ra) * 128 + (klo + 2 * ks) * 16);
            ldmx4(a[mi][0], a[mi][1], a[mi][2], a[mi][3], ad);
        }
#pragma unroll
        for (int p = 0; p < WNI / 2; ++p) {
            uint32_t ad = sB + swz((wn + p * 16 + brow) * 128 + (bk + 2 * ks) * 16);
            uint32_t r0, r1, r2, r3;
            ldmx4(r0, r1, r2, r3, ad);
            b[2 * p][0] = r0; b[2 * p][1] = r1;
            b[2 * p + 1][0] = r2; b[2 * p + 1][1] = r3;
        }
    };

    // Prologue: fill NSTG-1 stages (the last buffer is filled inside iter 0).
#pragma unroll
    for (int s = 0; s < NSTG - 1; s++) {
        load_stage<BNT, NSTG>(A, B, ldA, ldB, sb, s);
        cp_commit();
    }

    for (int kt = 0; kt < kIters; ++kt) {
        asm volatile("cp.async.wait_group %0;\n" ::"n"(NSTG - 2) : "memory");
        __syncthreads();
        // Load stage kt+NSTG-1 into buffer (kt-1)%NSTG: consumed in iter kt-1,
        // all warps are past it (barrier above). Overlaps this iter's MMAs.
        if (kt + NSTG - 1 < kIters)
            load_stage<BNT, NSTG>(A, B, ldA, ldB, sb, kt + NSTG - 1);
        cp_commit();  // constant group count

        const uint32_t sA = sb + (kt % NSTG) * STG;
        const uint32_t sB = sA + AST;
        uint32_t a[2][4][4], b[2][WNI][2];
        lda_frags(sA, sB, 0, a[0], b[0]);
#pragma unroll
        for (int ks = 0; ks < 4; ++ks) {
            const int cur = ks & 1;
            if (ks < 3) lda_frags(sA, sB, ks + 1, a[cur ^ 1], b[cur ^ 1]);
#pragma unroll
            for (int mi = 0; mi < 4; ++mi)
#pragma unroll
                for (int ni = 0; ni < WNI; ++ni)
                    mma_bf16(c[mi][ni], a[cur][mi], b[cur][ni]);
        }
    }
    __syncthreads();  // protect smem reuse by caller epilogues
}

// ---------------------------------------------------------------------------
// Fused pre-pass: W transpose, xs fp32->bf16, bv, out[0] = -sum(alphas).
constexpr int TW_BLK = (FD / 32) * (KD / 64);  // 8192
constexpr int CV_BLK = 2048;
constexpr int BV_BLK = 16;
constexpr int PRE_BLK = TW_BLK + CV_BLK + BV_BLK + 1;
__global__ void __launch_bounds__(256) k_pre(const float* __restrict__ xs,
                                             const float* __restrict__ W,
                                             const int* __restrict__ ys,
                                             const float* __restrict__ alphas,
                                             float* __restrict__ out) {
    const int bid = blockIdx.x;
    const int tid = threadIdx.x;
    if (bid < TW_BLK) {  // transpose 64(k) x 32(n) tile of W
        __shared__ float s[64][33];
        const int nb = (bid & 63) * 32, kb = (bid >> 6) * 64;
        const int tx = tid & 31, ty = tid >> 5;
#pragma unroll
        for (int r = 0; r < 64; r += 8)
            s[ty + r][tx] = W[(size_t)(kb + ty + r) * FD + nb + tx];
        __syncthreads();
#pragma unroll
        for (int rr = 0; rr < 4; rr++) {
            int n = ty + rr * 8;
            __nv_bfloat162 v = __floats2bfloat162_rn(s[2 * tx][n], s[2 * tx + 1][n]);
            *(__nv_bfloat162*)(g_Wt + (size_t)(nb + n) * KD + kb + 2 * tx) = v;
        }
    } else if (bid < TW_BLK + CV_BLK) {  // convert xs
        size_t i = (size_t)(bid - TW_BLK) * 256 + tid;
        const size_t n4 = (size_t)NP * KD / 4;
        const size_t stride = (size_t)CV_BLK * 256;
        __nv_bfloat162* o = (__nv_bfloat162*)g_xsb;
        const float4* in = (const float4*)xs;
        for (; i < n4; i += stride) {
            float4 v = in[i];
            o[2 * i] = __floats2bfloat162_rn(v.x, v.y);
            o[2 * i + 1] = __floats2bfloat162_rn(v.z, v.w);
        }
    } else if (bid < TW_BLK + CV_BLK + BV_BLK) {  // bv
        const int i = (bid - TW_BLK - CV_BLK) * 256 + tid;
        g_bv[i] = alphas[i] * (float)(2 * ys[i] - 1);
    } else {  // out[0] = -sum(alphas)
        float s = 0.f;
        for (int t = tid; t < NP; t += 256) s += alphas[t];
#pragma unroll
        for (int o = 16; o > 0; o >>= 1) s += __shfl_xor_sync(0xffffffffu, s, o);
        __shared__ float red[8];
        if ((tid & 31) == 0) red[tid >> 5] = s;
        __syncthreads();
        if (tid == 0) {
            float t = 0.f;
            for (int q = 0; q < 8; q++) t += red[q];
            out[0] = -t;
        }
    }
}

// GEMM1 split-K: slab z = xs[:, zKQ:(z+1)KQ] @ W[zKQ:(z+1)KQ, :], bf16 stores.
__global__ void __launch_bounds__(256, 1) k_gemm1() {
    float c[4][8][4];
#pragma unroll
    for (int i = 0; i < 4; i++)
#pragma unroll
        for (int j = 0; j < 8; j++)
#pragma unroll
            for (int k = 0; k < 4; k++) c[i][j][k] = 0.f;
    const int rowB = blockIdx.y * 128, colB = blockIdx.x * 256;
    const size_t koff = (size_t)blockIdx.z * KQ;
    gemm_mainloop<256, 8, 4>(g_xsb + (size_t)rowB * KD + koff,
                             g_Wt + (size_t)colB * KD + koff, KD, KD, KQ / BK, c);
    __nv_bfloat16* slab = g_Xh + (size_t)blockIdx.z * NPFD;
    const int lane = threadIdx.x & 31, warp = threadIdx.x >> 5;
    const int wm = (warp >> 2) * 64, wn = (warp & 3) * 64;
#pragma unroll
    for (int mi = 0; mi < 4; mi++) {
        const int r0 = rowB + wm + mi * 16 + (lane >> 2);
#pragma unroll
        for (int ni = 0; ni < 8; ni++) {
            const int c0 = colB + wn + ni * 8 + (lane & 3) * 2;
            *(__nv_bfloat162*)(slab + (size_t)r0 * FD + c0) =
                __floats2bfloat162_rn(c[mi][ni][0], c[mi][ni][1]);
            *(__nv_bfloat162*)(slab + (size_t)(r0 + 8) * FD + c0) =
                __floats2bfloat162_rn(c[mi][ni][2], c[mi][ni][3]);
        }
    }
}

// Combine: sum 4 bf16 slabs in fp32 -> bf16 g_Xb + row norms from ROUNDED
// values (exact diagonal cancellation in GEMM2). Warp per row.
__global__ void __launch_bounds__(256) k_combine() {
    const int row = blockIdx.x * 8 + (threadIdx.x >> 5);
    const int lane = threadIdx.x & 31;
    const uint2* s0 = (const uint2*)(g_Xh + (size_t)row * FD);
    const uint2* s1 = (const uint2*)(g_Xh + NPFD + (size_t)row * FD);
    const uint2* s2 = (const uint2*)(g_Xh + 2 * NPFD + (size_t)row * FD);
    const uint2* s3 = (const uint2*)(g_Xh + 3 * NPFD + (size_t)row * FD);
    uint2* dst = (uint2*)(g_Xb + (size_t)row * FD);
    float ss = 0.f;
#pragma unroll
    for (int it = 0; it < 16; it++) {
        const int idx = it * 32 + lane;
        uint2 u0 = s0[idx], u1 = s1[idx], u2 = s2[idx], u3 = s3[idx];
        const __nv_bfloat162* h0 = (const __nv_bfloat162*)&u0;
        const __nv_bfloat162* h1 = (const __nv_bfloat162*)&u1;
        const __nv_bfloat162* h2 = (const __nv_bfloat162*)&u2;
        const __nv_bfloat162* h3 = (const __nv_bfloat162*)&u3;
        uint2 w;
        __nv_bfloat162* hw = (__nv_bfloat162*)&w;
#pragma unroll
        for (int q = 0; q < 2; q++) {
            float2 f0 = __bfloat1622float2(h0[q]), f1 = __bfloat1622float2(h1[q]);
            float2 f2 = __bfloat1622float2(h2[q]), f3 = __bfloat1622float2(h3[q]);
            float vx = (f0.x + f1.x) + (f2.x + f3.x);
            float vy = (f0.y + f1.y) + (f2.y + f3.y);
            __nv_bfloat162 bb = __floats2bfloat162_rn(vx, vy);
            hw[q] = bb;
            float2 fb = __bfloat1622float2(bb);
            ss += fb.x * fb.x + fb.y * fb.y;
        }
        dst[idx] = w;
    }
#pragma unroll
    for (int o = 16; o > 0; o >>= 1) ss += __shfl_xor_sync(0xffffffffu, ss, o);
    if (lane == 0) g_sq[row] = ss;
}

// GEMM2 fused: 128(M) x 256(N) tiles, WNI=8, occ-1 (GEMM1's measured-best
// config). Triangle: keep (ti, tj) if tj >= ti>>1 (272 CTAs); boundary tile
// (ti>>1 == tj) gets per-element weights. Result -> atomicAdd(out).
__global__ void __launch_bounds__(256, 1) k_gemm2(float* __restrict__ out) {
    int ti = 0, rem = blockIdx.x;
    while (rem >= 16 - (ti >> 1)) { rem -= 16 - (ti >> 1); ti++; }
    const int tj = (ti >> 1) + rem;
    float c[4][8][4];
#pragma unroll
    for (int i = 0; i < 4; i++)
#pragma unroll
        for (int j = 0; j < 8; j++)
#pragma unroll
            for (int k = 0; k < 4; k++) c[i][j][k] = 0.f;
    gemm_mainloop<256, 8, 4>(g_Xb + (size_t)ti * 128 * FD,
                             g_Xb + (size_t)tj * 256 * FD, FD, FD, FD / BK, c);
    const int lane = threadIdx.x & 31, warp = threadIdx.x >> 5;
    const int wm = (warp >> 2) * 64, wn = (warp & 3) * 64;
    const bool bnd = ((ti >> 1) == tj);
    float acc = 0.f;
#pragma unroll
    for (int mi = 0; mi < 4; mi++) {
        const int i0 = ti * 128 + wm + mi * 16 + (lane >> 2);
        const int i1 = i0 + 8;
        const float sqi0 = g_sq[i0], sqi1 = g_sq[i1];
        const float bi0 = g_bv[i0], bi1 = g_bv[i1];
#pragma unroll
        for (int ni = 0; ni < 8; ni++) {
            const int j0 = tj * 256 + wn + ni * 8 + (lane & 3) * 2;
            const int j1 = j0 + 1;
            const float sqj0 = g_sq[j0], sqj1 = g_sq[j1];
            const float bj0 = g_bv[j0], bj1 = g_bv[j1];
            float e00 = bi0 * bj0 * __expf(-GAMMA * fmaxf(sqi0 + sqj0 - 2.f * c[mi][ni][0], 0.f));
            float e01 = bi0 * bj1 * __expf(-GAMMA * fmaxf(sqi0 + sqj1 - 2.f * c[mi][ni][1], 0.f));
            float e10 = bi1 * bj0 * __expf(-GAMMA * fmaxf(sqi1 + sqj0 - 2.f * c[mi][ni][2], 0.f));
            float e11 = bi1 * bj1 * __expf(-GAMMA * fmaxf(sqi1 + sqj1 - 2.f * c[mi][ni][3], 0.f));
            if (bnd) {
                auto wgt = [](int j, int i) {
                    return (j > i) ? 2.f : ((j == i) ? 1.f : 0.f);
                };
                acc += wgt(j0, i0) * e00 + wgt(j1, i0) * e01 +
                       wgt(j0, i1) * e10 + wgt(j1, i1) * e11;
            } else {
                acc += 2.f * (e00 + e01 + e10 + e11);
            }
        }
    }
#pragma unroll
    for (int o = 16; o > 0; o >>= 1) acc += __shfl_xor_sync(0xffffffffu, acc, o);
    extern __shared__ char smem[];
    float* red = (float*)smem;
    if (lane == 0) red[warp] = acc;
    __syncthreads();
    if (threadIdx.x == 0) {
        float s = 0.f;
        for (int q = 0; q < 8; q++) s += red[q];
        atomicAdd(out, 0.5f * s);
    }
}

// ---------------------------------------------------------------------------
constexpr int SMEM_GG = 4 * (128 * 128 + 256 * 128);  // 192 KB
constexpr int G2_GRID = 272;  // sum over ti of (16 - ti/2)

extern "C" void kernel_launch(void* const* d_in, const int* in_sizes, int n_in,
                              void* d_out, int out_size) {
    (void)in_sizes; (void)n_in; (void)out_size;
    const float* xs = (const float*)d_in[0];
    const float* W = (const float*)d_in[1];
    const int* ys = (const int*)d_in[2];
    const float* alphas = (const float*)d_in[3];
    float* out = (float*)d_out;

    cudaFuncSetAttribute(k_gemm1, cudaFuncAttributeMaxDynamicSharedMemorySize,
                         SMEM_GG);
    cudaFuncSetAttribute(k_gemm2, cudaFuncAttributeMaxDynamicSharedMemorySize,
                         SMEM_GG);

    k_pre<<<PRE_BLK, 256>>>(xs, W, ys, alphas, out);
    k_gemm1<<<dim3(FD / 256, NP / 128, KSPLIT), 256, SMEM_GG>>>();
    k_combine<<<NP / 8, 256>>>();
    k_gemm2<<<G2_GRID, 256, SMEM_GG>>>(out);
}